// round 3
// baseline (speedup 1.0000x reference)
#include <cuda_runtime.h>
#include <math.h>

// Problem constants
#define CB    4       // batch
#define TQ    1024    // query tokens
#define TCX   2048    // context tokens
#define CD    1024    // d_model
#define NH    16      // heads
#define HD    64      // head dim
#define MQ    (CB*TQ)    // 4096
#define MKV   (CB*TCX)   // 8192
#define ATT_SCALE 0.125f // 64^-0.5
#define LN_EPS 1e-5f
#define Q_EPS  1e-5f

// ---------------- device scratch (no cudaMalloc allowed) ----------------
__device__ float g_xn[MQ*CD];
__device__ float g_q [MQ*CD];
__device__ float g_k [MKV*CD];
__device__ float g_v [MKV*CD];
__device__ float g_attn[MQ*CD];
__device__ float g_wq[CD*CD];
__device__ float g_wk[CD*CD];
__device__ float g_wv[CD*CD];
__device__ float g_wo[CD*CD];
__device__ float g_partial[4][256];
__device__ float g_gamma[4];

// ---------------- |W| mean (deterministic two-pass) ----------------
__global__ __launch_bounds__(256) void absmean_partial(
    const float* __restrict__ W0, const float* __restrict__ W1,
    const float* __restrict__ W2, const float* __restrict__ W3)
{
    const float* W = (blockIdx.y == 0) ? W0 : (blockIdx.y == 1) ? W1
                   : (blockIdx.y == 2) ? W2 : W3;
    __shared__ float sh[256];
    int base = blockIdx.x * 4096;
    float acc = 0.f;
    for (int i = threadIdx.x; i < 4096; i += 256)
        acc += fabsf(W[base + i]);
    sh[threadIdx.x] = acc;
    __syncthreads();
    for (int o = 128; o > 0; o >>= 1) {
        if (threadIdx.x < o) sh[threadIdx.x] += sh[threadIdx.x + o];
        __syncthreads();
    }
    if (threadIdx.x == 0) g_partial[blockIdx.y][blockIdx.x] = sh[0];
}

__global__ __launch_bounds__(256) void absmean_final()
{
    __shared__ float sh[256];
    sh[threadIdx.x] = g_partial[blockIdx.x][threadIdx.x];
    __syncthreads();
    for (int o = 128; o > 0; o >>= 1) {
        if (threadIdx.x < o) sh[threadIdx.x] += sh[threadIdx.x + o];
        __syncthreads();
    }
    if (threadIdx.x == 0)
        g_gamma[blockIdx.x] = sh[0] / (float)(CD * CD);
}

// ---------------- ternary quantization ----------------
__global__ __launch_bounds__(256) void quantize_w(
    const float* __restrict__ W0, const float* __restrict__ W1,
    const float* __restrict__ W2, const float* __restrict__ W3)
{
    int w = blockIdx.y;
    const float* W = (w == 0) ? W0 : (w == 1) ? W1 : (w == 2) ? W2 : W3;
    float* Wd = (w == 0) ? g_wq : (w == 1) ? g_wk : (w == 2) ? g_wv : g_wo;
    float g  = g_gamma[w];
    float gd = g + Q_EPS;
    int idx0 = blockIdx.x * 256 + threadIdx.x;   // 1024 blocks * 256 = 262144
    #pragma unroll
    for (int r = 0; r < 4; r++) {
        int i = idx0 + r * 262144;
        float t = rintf(W[i] / gd);              // round-half-even, matches jnp
        t = fminf(fmaxf(t, -1.f), 1.f);
        Wd[i] = t * g;
    }
}

// ---------------- layernorm ----------------
__global__ __launch_bounds__(256) void layernorm_k(
    const float* __restrict__ x, const float* __restrict__ gamma,
    const float* __restrict__ beta)
{
    int row = blockIdx.x;
    const float* xr = x + (size_t)row * CD;
    __shared__ float s1[256], s2[256];
    float a = 0.f, b = 0.f;
    for (int i = threadIdx.x; i < CD; i += 256) {
        float v = xr[i];
        a += v; b += v * v;
    }
    s1[threadIdx.x] = a; s2[threadIdx.x] = b;
    __syncthreads();
    for (int o = 128; o > 0; o >>= 1) {
        if (threadIdx.x < o) {
            s1[threadIdx.x] += s1[threadIdx.x + o];
            s2[threadIdx.x] += s2[threadIdx.x + o];
        }
        __syncthreads();
    }
    float mu  = s1[0] / (float)CD;
    float var = s2[0] / (float)CD - mu * mu;
    float rstd = rsqrtf(var + LN_EPS);
    for (int i = threadIdx.x; i < CD; i += 256)
        g_xn[(size_t)row * CD + i] = (xr[i] - mu) * rstd * gamma[i] + beta[i];
}

// ---------------- fp32 NT GEMM: out[M,N] = A[M,K] * W[N,K]^T + bias (+resid) ----------------
// K = N = CD = 1024.  BM=BN=128, BK=8, 256 threads, 8x8 micro-tile per thread.
__global__ __launch_bounds__(256) void gemm_nt(
    const float* __restrict__ A, const float* __restrict__ W,
    const float* __restrict__ bias, const float* __restrict__ resid,
    float* __restrict__ out)
{
    __shared__ float As[8][128];
    __shared__ float Bs[8][128];

    const int bm = blockIdx.y * 128;
    const int bn = blockIdx.x * 128;
    const int tid = threadIdx.x;
    const int tx = tid & 15;      // 0..15 -> output cols tx*8
    const int ty = tid >> 4;      // 0..15 -> output rows ty*8

    const int lr = tid >> 1;          // 0..127 load row
    const int lk = (tid & 1) * 4;     // 0 or 4

    float acc[8][8];
    #pragma unroll
    for (int i = 0; i < 8; i++)
        #pragma unroll
        for (int j = 0; j < 8; j++) acc[i][j] = 0.f;

    for (int k0 = 0; k0 < CD; k0 += 8) {
        float4 va = *(const float4*)&A[(size_t)(bm + lr) * CD + k0 + lk];
        float4 vb = *(const float4*)&W[(size_t)(bn + lr) * CD + k0 + lk];
        As[lk + 0][lr] = va.x; As[lk + 1][lr] = va.y;
        As[lk + 2][lr] = va.z; As[lk + 3][lr] = va.w;
        Bs[lk + 0][lr] = vb.x; Bs[lk + 1][lr] = vb.y;
        Bs[lk + 2][lr] = vb.z; Bs[lk + 3][lr] = vb.w;
        __syncthreads();

        #pragma unroll
        for (int k = 0; k < 8; k++) {
            float4 a0 = *(const float4*)&As[k][ty * 8];
            float4 a1 = *(const float4*)&As[k][ty * 8 + 4];
            float4 b0 = *(const float4*)&Bs[k][tx * 8];
            float4 b1 = *(const float4*)&Bs[k][tx * 8 + 4];
            float ar[8] = {a0.x, a0.y, a0.z, a0.w, a1.x, a1.y, a1.z, a1.w};
            float br[8] = {b0.x, b0.y, b0.z, b0.w, b1.x, b1.y, b1.z, b1.w};
            #pragma unroll
            for (int i = 0; i < 8; i++)
                #pragma unroll
                for (int j = 0; j < 8; j++)
                    acc[i][j] = fmaf(ar[i], br[j], acc[i][j]);
        }
        __syncthreads();
    }

    #pragma unroll
    for (int i = 0; i < 8; i++) {
        int gr = bm + ty * 8 + i;
        #pragma unroll
        for (int j = 0; j < 8; j++) {
            int gc = bn + tx * 8 + j;
            float v = acc[i][j] + bias[gc];
            if (resid) v += resid[(size_t)gr * CD + gc];
            out[(size_t)gr * CD + gc] = v;
        }
    }
}

// ---------------- flash attention (fp32, 64x64 tiles, online softmax) ----------------
// grid: (TQ/64, CB*NH), block: 256 threads, dynamic smem.
__global__ __launch_bounds__(256) void attention_k()
{
    extern __shared__ float smem[];
    float* Qt  = smem;               // [64 d][65]  (d-major)
    float* Kt  = Qt + 64 * 65;       // [64 d][65]
    float* Vs  = Kt + 64 * 65;       // [64 kv][65] (kv-major)
    float* Ss  = Vs + 64 * 65;       // [64 q][65]
    float* m_s = Ss + 64 * 65;       // [64]
    float* l_s = m_s + 64;           // [64]
    float* c_s = l_s + 64;           // [64]

    const int qblk = blockIdx.x;
    const int bh   = blockIdx.y;
    const int b = bh / NH, h = bh % NH;
    const int tid = threadIdx.x;
    const int tx = tid & 15;   // cols tx*4
    const int ty = tid >> 4;   // rows ty*4

    const float* Qbase = g_q + ((size_t)(b * TQ + qblk * 64)) * CD + h * HD;
    const float* Kbase = g_k + ((size_t)(b * TCX)) * CD + h * HD;
    const float* Vbase = g_v + ((size_t)(b * TCX)) * CD + h * HD;

    // load Q tile (transposed to d-major)
    for (int i = tid; i < 64 * 64; i += 256) {
        int q = i >> 6, d = i & 63;
        Qt[d * 65 + q] = Qbase[(size_t)q * CD + d];
    }
    if (tid < 64) { m_s[tid] = -1e30f; l_s[tid] = 0.f; }

    float O[4][4];
    #pragma unroll
    for (int i = 0; i < 4; i++)
        #pragma unroll
        for (int j = 0; j < 4; j++) O[i][j] = 0.f;

    for (int t = 0; t < TCX / 64; t++) {
        __syncthreads();   // prev iter done reading Kt/Vs/Ss; Q ready on first iter
        for (int i = tid; i < 64 * 64; i += 256) {
            int r = i >> 6, d = i & 63;
            float kv = Kbase[(size_t)(t * 64 + r) * CD + d];
            float vv = Vbase[(size_t)(t * 64 + r) * CD + d];
            Kt[d * 65 + r] = kv;
            Vs[r * 65 + d] = vv;
        }
        __syncthreads();

        // S = Q K^T * scale  (4x4 per thread)
        float sa[4][4];
        #pragma unroll
        for (int i = 0; i < 4; i++)
            #pragma unroll
            for (int j = 0; j < 4; j++) sa[i][j] = 0.f;
        #pragma unroll 4
        for (int d = 0; d < 64; d++) {
            float qa[4], kb[4];
            #pragma unroll
            for (int i = 0; i < 4; i++) qa[i] = Qt[d * 65 + ty * 4 + i];
            #pragma unroll
            for (int j = 0; j < 4; j++) kb[j] = Kt[d * 65 + tx * 4 + j];
            #pragma unroll
            for (int i = 0; i < 4; i++)
                #pragma unroll
                for (int j = 0; j < 4; j++)
                    sa[i][j] = fmaf(qa[i], kb[j], sa[i][j]);
        }
        #pragma unroll
        for (int i = 0; i < 4; i++)
            #pragma unroll
            for (int j = 0; j < 4; j++)
                Ss[(ty * 4 + i) * 65 + tx * 4 + j] = sa[i][j] * ATT_SCALE;
        __syncthreads();

        // online softmax per row (64 threads)
        if (tid < 64) {
            int r = tid;
            float mo = m_s[r];
            float mt = mo;
            for (int j = 0; j < 64; j++) mt = fmaxf(mt, Ss[r * 65 + j]);
            float corr = expf(mo - mt);
            float ls = 0.f;
            for (int j = 0; j < 64; j++) {
                float p = expf(Ss[r * 65 + j] - mt);
                Ss[r * 65 + j] = p;
                ls += p;
            }
            l_s[r] = l_s[r] * corr + ls;
            m_s[r] = mt;
            c_s[r] = corr;
        }
        __syncthreads();

        // rescale O and accumulate P @ V
        #pragma unroll
        for (int i = 0; i < 4; i++) {
            float c = c_s[ty * 4 + i];
            #pragma unroll
            for (int j = 0; j < 4; j++) O[i][j] *= c;
        }
        #pragma unroll 4
        for (int kv = 0; kv < 64; kv++) {
            float pa[4], vb[4];
            #pragma unroll
            for (int i = 0; i < 4; i++) pa[i] = Ss[(ty * 4 + i) * 65 + kv];
            #pragma unroll
            for (int j = 0; j < 4; j++) vb[j] = Vs[kv * 65 + tx * 4 + j];
            #pragma unroll
            for (int i = 0; i < 4; i++)
                #pragma unroll
                for (int j = 0; j < 4; j++)
                    O[i][j] = fmaf(pa[i], vb[j], O[i][j]);
        }
    }
    __syncthreads();

    float* Obase = g_attn + ((size_t)(b * TQ + qblk * 64)) * CD + h * HD;
    #pragma unroll
    for (int i = 0; i < 4; i++) {
        int r = ty * 4 + i;
        float inv = 1.f / l_s[r];
        #pragma unroll
        for (int j = 0; j < 4; j++)
            Obase[(size_t)r * CD + tx * 4 + j] = O[i][j] * inv;
    }
}

// ---------------- host launch ----------------
extern "C" void kernel_launch(void* const* d_in, const int* in_sizes, int n_in,
                              void* d_out, int out_size)
{
    const float* x    = (const float*)d_in[0];
    const float* ctx  = (const float*)d_in[1];
    const float* Wq   = (const float*)d_in[2];
    const float* bq   = (const float*)d_in[3];
    const float* Wk   = (const float*)d_in[4];
    const float* bk   = (const float*)d_in[5];
    const float* Wv   = (const float*)d_in[6];
    const float* bv   = (const float*)d_in[7];
    const float* Wo   = (const float*)d_in[8];
    const float* bo   = (const float*)d_in[9];
    const float* ln_g = (const float*)d_in[10];
    const float* ln_b = (const float*)d_in[11];
    float* out = (float*)d_out;

    // device scratch addresses (host side; not a stream op, capture-safe)
    float *p_xn, *p_q, *p_k, *p_v, *p_attn, *p_wq, *p_wk, *p_wv, *p_wo;
    cudaGetSymbolAddress((void**)&p_xn,   g_xn);
    cudaGetSymbolAddress((void**)&p_q,    g_q);
    cudaGetSymbolAddress((void**)&p_k,    g_k);
    cudaGetSymbolAddress((void**)&p_v,    g_v);
    cudaGetSymbolAddress((void**)&p_attn, g_attn);
    cudaGetSymbolAddress((void**)&p_wq,   g_wq);
    cudaGetSymbolAddress((void**)&p_wk,   g_wk);
    cudaGetSymbolAddress((void**)&p_wv,   g_wv);
    cudaGetSymbolAddress((void**)&p_wo,   g_wo);

    // 1. quantization scales
    absmean_partial<<<dim3(256, 4), 256>>>(Wq, Wk, Wv, Wo);
    absmean_final<<<4, 256>>>();
    quantize_w<<<dim3(1024, 4), 256>>>(Wq, Wk, Wv, Wo);

    // 2. layernorm
    layernorm_k<<<MQ, 256>>>(x, ln_g, ln_b);

    // 3. projections
    gemm_nt<<<dim3(CD / 128, MQ  / 128), 256>>>(p_xn, p_wq, bq, nullptr, p_q);
    gemm_nt<<<dim3(CD / 128, MKV / 128), 256>>>(ctx,  p_wk, bk, nullptr, p_k);
    gemm_nt<<<dim3(CD / 128, MKV / 128), 256>>>(ctx,  p_wv, bv, nullptr, p_v);

    // 4. attention
    size_t att_smem = (4 * 64 * 65 + 3 * 64) * sizeof(float);  // ~67.3 KB
    cudaFuncSetAttribute(attention_k, cudaFuncAttributeMaxDynamicSharedMemorySize,
                         (int)att_smem);
    attention_k<<<dim3(TQ / 64, CB * NH), 256, att_smem>>>();

    // 5. output projection + bias + residual
    gemm_nt<<<dim3(CD / 128, MQ / 128), 256>>>(p_attn, p_wo, bo, x, out);
}

// round 6
// speedup vs baseline: 2.6427x; 2.6427x over previous
#include <cuda_runtime.h>
#include <math.h>

// Problem constants
#define CB    4       // batch
#define TQ    1024    // query tokens
#define TCX   2048    // context tokens
#define CD    1024    // d_model
#define NH    16      // heads
#define HD    64      // head dim
#define MQ    (CB*TQ)    // 4096
#define MKV   (CB*TCX)   // 8192
#define ATT_SCALE 0.125f // 64^-0.5
#define LN_EPS 1e-5f
#define Q_EPS  1e-5f

// ---------------- device scratch (no cudaMalloc allowed) ----------------
__device__ float    g_xn[MQ*CD];
__device__ float    g_q [MQ*CD];
__device__ float    g_k [MKV*CD];
__device__ float    g_v [MKV*CD];
__device__ float    g_attn[MQ*CD];
__device__ unsigned g_wq[CD*CD];   // ternary weights, tf32-encoded (exact)
__device__ unsigned g_wk[CD*CD];
__device__ unsigned g_wv[CD*CD];
__device__ unsigned g_wo[CD*CD];
__device__ float    g_partial[4][256];
__device__ float    g_gamma[4];

// ---------------- tf32 helpers ----------------
__device__ __forceinline__ unsigned f2tf32(float f) {
    unsigned u;
    asm("cvt.rna.tf32.f32 %0, %1;" : "=r"(u) : "f"(f));
    return u;
}

__device__ __forceinline__ void mma_tf32(
    float& c0, float& c1, float& c2, float& c3,
    unsigned a0, unsigned a1, unsigned a2, unsigned a3,
    unsigned b0, unsigned b1)
{
    asm("mma.sync.aligned.m16n8k8.row.col.f32.tf32.tf32.f32 "
        "{%0,%1,%2,%3},{%4,%5,%6,%7},{%8,%9},{%0,%1,%2,%3};"
        : "+f"(c0), "+f"(c1), "+f"(c2), "+f"(c3)
        : "r"(a0), "r"(a1), "r"(a2), "r"(a3), "r"(b0), "r"(b1));
}

// ---------------- |W| mean (deterministic two-pass) ----------------
__global__ __launch_bounds__(256) void absmean_partial(
    const float* __restrict__ W0, const float* __restrict__ W1,
    const float* __restrict__ W2, const float* __restrict__ W3)
{
    const float* W = (blockIdx.y == 0) ? W0 : (blockIdx.y == 1) ? W1
                   : (blockIdx.y == 2) ? W2 : W3;
    __shared__ float sh[256];
    int base = blockIdx.x * 4096;
    float acc = 0.f;
    for (int i = threadIdx.x; i < 4096; i += 256)
        acc += fabsf(W[base + i]);
    sh[threadIdx.x] = acc;
    __syncthreads();
    for (int o = 128; o > 0; o >>= 1) {
        if (threadIdx.x < o) sh[threadIdx.x] += sh[threadIdx.x + o];
        __syncthreads();
    }
    if (threadIdx.x == 0) g_partial[blockIdx.y][blockIdx.x] = sh[0];
}

__global__ __launch_bounds__(256) void absmean_final()
{
    __shared__ float sh[256];
    sh[threadIdx.x] = g_partial[blockIdx.x][threadIdx.x];
    __syncthreads();
    for (int o = 128; o > 0; o >>= 1) {
        if (threadIdx.x < o) sh[threadIdx.x] += sh[threadIdx.x + o];
        __syncthreads();
    }
    if (threadIdx.x == 0)
        g_gamma[blockIdx.x] = sh[0] / (float)(CD * CD);
}

// ---------------- ternary quantization (store ternary EXACT in tf32) ----------------
__global__ __launch_bounds__(256) void quantize_w(
    const float* __restrict__ W0, const float* __restrict__ W1,
    const float* __restrict__ W2, const float* __restrict__ W3)
{
    int w = blockIdx.y;
    const float* W = (w == 0) ? W0 : (w == 1) ? W1 : (w == 2) ? W2 : W3;
    unsigned* Wd = (w == 0) ? g_wq : (w == 1) ? g_wk : (w == 2) ? g_wv : g_wo;
    float g  = g_gamma[w];
    float gd = g + Q_EPS;
    int idx0 = blockIdx.x * 256 + threadIdx.x;
    #pragma unroll
    for (int r = 0; r < 4; r++) {
        int i = idx0 + r * 262144;
        float t = rintf(W[i] / gd);              // round-half-even, matches jnp
        t = fminf(fmaxf(t, -1.f), 1.f);
        Wd[i] = f2tf32(t);                       // exact: ternary
    }
}

// ---------------- layernorm ----------------
__global__ __launch_bounds__(256) void layernorm_k(
    const float* __restrict__ x, const float* __restrict__ gamma,
    const float* __restrict__ beta)
{
    int row = blockIdx.x;
    const float* xr = x + (size_t)row * CD;
    __shared__ float s1[256], s2[256];
    float a = 0.f, b = 0.f;
    for (int i = threadIdx.x; i < CD; i += 256) {
        float v = xr[i];
        a += v; b += v * v;
    }
    s1[threadIdx.x] = a; s2[threadIdx.x] = b;
    __syncthreads();
    for (int o = 128; o > 0; o >>= 1) {
        if (threadIdx.x < o) {
            s1[threadIdx.x] += s1[threadIdx.x + o];
            s2[threadIdx.x] += s2[threadIdx.x + o];
        }
        __syncthreads();
    }
    float mu  = s1[0] / (float)CD;
    float var = s2[0] / (float)CD - mu * mu;
    float rstd = rsqrtf(var + LN_EPS);
    for (int i = threadIdx.x; i < CD; i += 256)
        g_xn[(size_t)row * CD + i] = (xr[i] - mu) * rstd * gamma[i] + beta[i];
}

// ---------------- tf32 tensor-core NT GEMM ----------------
// out[M,1024] = (A[M,1024] @ Wt[1024,1024]^T) * gamma + bias (+resid)
// 128x128 block tile, BK=16, 8 warps (2x4), warp tile 64x32, mma m16n8k8.
#define GLD 20  // padded smem leading dim (floats) -> conflict-free frag loads

__global__ __launch_bounds__(256) void gemm_tf32(
    const float* __restrict__ A, const unsigned* __restrict__ W,
    const float* __restrict__ bias, const float* __restrict__ resid,
    float* __restrict__ out, int gidx)
{
    __shared__ unsigned As[128 * GLD];
    __shared__ unsigned Ws[128 * GLD];

    const int tid = threadIdx.x, lane = tid & 31, wid = tid >> 5;
    const int bm = blockIdx.y * 128, bn = blockIdx.x * 128;
    const int wm = (wid >> 2) * 64, wn = (wid & 3) * 32;
    const int lr4 = lane >> 2, lc4 = lane & 3;

    float c[4][4][4];
    #pragma unroll
    for (int i = 0; i < 4; i++)
        #pragma unroll
        for (int j = 0; j < 4; j++)
            #pragma unroll
            for (int r = 0; r < 4; r++) c[i][j][r] = 0.f;

    for (int k0 = 0; k0 < CD; k0 += 16) {
        #pragma unroll
        for (int h = 0; h < 2; h++) {
            int j = tid + h * 256;
            int r = j >> 2, q = (j & 3) * 4;
            float4 va = *(const float4*)&A[(size_t)(bm + r) * CD + k0 + q];
            uint4  vb = *(const uint4 *)&W[(size_t)(bn + r) * CD + k0 + q];
            unsigned* pa = &As[r * GLD + q];
            unsigned* pb = &Ws[r * GLD + q];
            pa[0] = f2tf32(va.x); pa[1] = f2tf32(va.y);
            pa[2] = f2tf32(va.z); pa[3] = f2tf32(va.w);
            pb[0] = vb.x; pb[1] = vb.y; pb[2] = vb.z; pb[3] = vb.w;
        }
        __syncthreads();

        #pragma unroll
        for (int ks = 0; ks < 2; ks++) {
            unsigned a[4][4], b[4][2];
            #pragma unroll
            for (int i = 0; i < 4; i++) {
                int r = wm + i * 16 + lr4;
                a[i][0] = As[r * GLD + ks * 8 + lc4];
                a[i][1] = As[(r + 8) * GLD + ks * 8 + lc4];
                a[i][2] = As[r * GLD + ks * 8 + lc4 + 4];
                a[i][3] = As[(r + 8) * GLD + ks * 8 + lc4 + 4];
            }
            #pragma unroll
            for (int j = 0; j < 4; j++) {
                int n = wn + j * 8 + lr4;
                b[j][0] = Ws[n * GLD + ks * 8 + lc4];
                b[j][1] = Ws[n * GLD + ks * 8 + lc4 + 4];
            }
            #pragma unroll
            for (int i = 0; i < 4; i++)
                #pragma unroll
                for (int j = 0; j < 4; j++)
                    mma_tf32(c[i][j][0], c[i][j][1], c[i][j][2], c[i][j][3],
                             a[i][0], a[i][1], a[i][2], a[i][3],
                             b[j][0], b[j][1]);
        }
        __syncthreads();
    }

    const float g = g_gamma[gidx];
    #pragma unroll
    for (int i = 0; i < 4; i++) {
        int r0 = bm + wm + i * 16 + lr4;
        #pragma unroll
        for (int j = 0; j < 4; j++) {
            int col = bn + wn + j * 8 + lc4 * 2;
            float b0v = bias[col], b1v = bias[col + 1];
            size_t i00 = (size_t)r0 * CD + col;
            size_t i10 = (size_t)(r0 + 8) * CD + col;
            float v00 = c[i][j][0] * g + b0v;
            float v01 = c[i][j][1] * g + b1v;
            float v10 = c[i][j][2] * g + b0v;
            float v11 = c[i][j][3] * g + b1v;
            if (resid) {
                v00 += resid[i00]; v01 += resid[i00 + 1];
                v10 += resid[i10]; v11 += resid[i10 + 1];
            }
            out[i00] = v00; out[i00 + 1] = v01;
            out[i10] = v10; out[i10 + 1] = v11;
        }
    }
}

// ---------------- flash attention, tf32 tensor cores ----------------
// 64 q-rows per block, 64-wide kv tiles, online softmax in fp32.
// 8 warps in a 4(m) x 2(n/d) grid; each warp: 16 q-rows x 32 cols.
#define ALD 68   // smem ld for Q/K/S (floats)
#define VLD 72   // smem ld for V (conflict-free B-frag loads)

__global__ __launch_bounds__(256) void attention_tf32()
{
    extern __shared__ float smem[];
    float* Qs = smem;                    // [64][ALD]
    float* Ks = Qs + 64 * ALD;           // [64][ALD]
    float* Ss = Ks + 64 * ALD;           // [64][ALD]  scores / probs
    float* Vs = Ss + 64 * ALD;           // [64][VLD]
    float* m_s = Vs + 64 * VLD;
    float* l_s = m_s + 64;
    float* c_s = l_s + 64;
    unsigned* Qu = (unsigned*)Qs;
    unsigned* Ku = (unsigned*)Ks;
    unsigned* Su = (unsigned*)Ss;
    unsigned* Vu = (unsigned*)Vs;

    const int tid = threadIdx.x, lane = tid & 31, wid = tid >> 5;
    const int qblk = blockIdx.x, bh = blockIdx.y;
    const int b = bh >> 4, h = bh & 15;
    const int lr4 = lane >> 2, lc4 = lane & 3;
    const int wr = (wid >> 1) * 16;      // warp q-row base
    const int wd = (wid & 1) * 32;       // warp col base (kv cols for S, d cols for O)

    const float* Qbase = g_q + ((size_t)(b * TQ + qblk * 64)) * CD + h * HD;
    const float* Kbase = g_k + ((size_t)(b * TCX)) * CD + h * HD;
    const float* Vbase = g_v + ((size_t)(b * TCX)) * CD + h * HD;

    // load Q tile, fold in softmax scale, convert to tf32
    for (int i = tid; i < 64 * 64; i += 256) {
        int q = i >> 6, d = i & 63;
        Qu[q * ALD + d] = f2tf32(Qbase[(size_t)q * CD + d] * ATT_SCALE);
    }
    if (tid < 64) { m_s[tid] = -1e30f; l_s[tid] = 0.f; }

    float o[4][4];
    #pragma unroll
    for (int j = 0; j < 4; j++)
        #pragma unroll
        for (int r = 0; r < 4; r++) o[j][r] = 0.f;

    for (int t = 0; t < TCX / 64; t++) {
        __syncthreads();   // prev iter done with Ss/Vs; Q+state ready on t=0
        // load K, V tiles (float4, tf32-convert)
        for (int i = tid; i < 1024; i += 256) {
            int r = i >> 4, dq = (i & 15) * 4;
            float4 kv = *(const float4*)&Kbase[(size_t)(t * 64 + r) * CD + dq];
            float4 vv = *(const float4*)&Vbase[(size_t)(t * 64 + r) * CD + dq];
            unsigned* pk = &Ku[r * ALD + dq];
            unsigned* pv = &Vu[r * VLD + dq];
            pk[0] = f2tf32(kv.x); pk[1] = f2tf32(kv.y);
            pk[2] = f2tf32(kv.z); pk[3] = f2tf32(kv.w);
            pv[0] = f2tf32(vv.x); pv[1] = f2tf32(vv.y);
            pv[2] = f2tf32(vv.z); pv[3] = f2tf32(vv.w);
        }
        __syncthreads();

        // S = Q K^T  (scale already folded into Q)
        float s[4][4];
        #pragma unroll
        for (int j = 0; j < 4; j++)
            #pragma unroll
            for (int r = 0; r < 4; r++) s[j][r] = 0.f;
        #pragma unroll
        for (int ks = 0; ks < 8; ks++) {
            unsigned a0 = Qu[(wr + lr4) * ALD + ks * 8 + lc4];
            unsigned a1 = Qu[(wr + lr4 + 8) * ALD + ks * 8 + lc4];
            unsigned a2 = Qu[(wr + lr4) * ALD + ks * 8 + lc4 + 4];
            unsigned a3 = Qu[(wr + lr4 + 8) * ALD + ks * 8 + lc4 + 4];
            #pragma unroll
            for (int j = 0; j < 4; j++) {
                int n = wd + j * 8 + lr4;
                unsigned b0 = Ku[n * ALD + ks * 8 + lc4];
                unsigned b1 = Ku[n * ALD + ks * 8 + lc4 + 4];
                mma_tf32(s[j][0], s[j][1], s[j][2], s[j][3], a0, a1, a2, a3, b0, b1);
            }
        }
        // write scores to smem (fp32)
        #pragma unroll
        for (int j = 0; j < 4; j++) {
            int colb = wd + j * 8 + lc4 * 2;
            Ss[(wr + lr4) * ALD + colb]     = s[j][0];
            Ss[(wr + lr4) * ALD + colb + 1] = s[j][1];
            Ss[(wr + lr4 + 8) * ALD + colb]     = s[j][2];
            Ss[(wr + lr4 + 8) * ALD + colb + 1] = s[j][3];
        }
        __syncthreads();

        // online softmax: 4 threads per row (within a warp), shfl combine
        {
            int row = tid >> 2, part = tid & 3;
            float* Sr = Ss + row * ALD + part * 16;
            float mt = -1e30f;
            #pragma unroll
            for (int cc = 0; cc < 16; cc++) mt = fmaxf(mt, Sr[cc]);
            mt = fmaxf(mt, __shfl_xor_sync(0xffffffffu, mt, 1));
            mt = fmaxf(mt, __shfl_xor_sync(0xffffffffu, mt, 2));
            float mo = m_s[row];
            float mn = fmaxf(mo, mt);
            float ls = 0.f;
            unsigned* SrU = (unsigned*)Sr;
            #pragma unroll
            for (int cc = 0; cc < 16; cc++) {
                float p = __expf(Sr[cc] - mn);
                ls += p;
                SrU[cc] = f2tf32(p);           // probs become tf32 for PV mma
            }
            ls += __shfl_xor_sync(0xffffffffu, ls, 1);
            ls += __shfl_xor_sync(0xffffffffu, ls, 2);
            if (part == 0) {
                float cr = __expf(mo - mn);
                c_s[row] = cr;
                l_s[row] = l_s[row] * cr + ls;
                m_s[row] = mn;
            }
        }
        __syncthreads();

        // rescale running O by correction factor
        float cr0 = c_s[wr + lr4];
        float cr1 = c_s[wr + lr4 + 8];
        #pragma unroll
        for (int j = 0; j < 4; j++) {
            o[j][0] *= cr0; o[j][1] *= cr0;
            o[j][2] *= cr1; o[j][3] *= cr1;
        }

        // O += P @ V
        #pragma unroll
        for (int ks = 0; ks < 8; ks++) {
            unsigned a0 = Su[(wr + lr4) * ALD + ks * 8 + lc4];
            unsigned a1 = Su[(wr + lr4 + 8) * ALD + ks * 8 + lc4];
            unsigned a2 = Su[(wr + lr4) * ALD + ks * 8 + lc4 + 4];
            unsigned a3 = Su[(wr + lr4 + 8) * ALD + ks * 8 + lc4 + 4];
            #pragma unroll
            for (int j = 0; j < 4; j++) {
                int n = wd + j * 8 + lr4;
                unsigned b0 = Vu[(ks * 8 + lc4) * VLD + n];
                unsigned b1 = Vu[(ks * 8 + lc4 + 4) * VLD + n];
                mma_tf32(o[j][0], o[j][1], o[j][2], o[j][3], a0, a1, a2, a3, b0, b1);
            }
        }
    }

    // epilogue: normalize and write
    float inv0 = 1.f / l_s[wr + lr4];
    float inv1 = 1.f / l_s[wr + lr4 + 8];
    float* Ob = g_attn + ((size_t)(b * TQ + qblk * 64)) * CD + h * HD;
    #pragma unroll
    for (int j = 0; j < 4; j++) {
        int col = wd + j * 8 + lc4 * 2;
        size_t i0 = (size_t)(wr + lr4) * CD + col;
        size_t i1 = (size_t)(wr + lr4 + 8) * CD + col;
        Ob[i0]     = o[j][0] * inv0;
        Ob[i0 + 1] = o[j][1] * inv0;
        Ob[i1]     = o[j][2] * inv1;
        Ob[i1 + 1] = o[j][3] * inv1;
    }
}

// ---------------- host launch ----------------
extern "C" void kernel_launch(void* const* d_in, const int* in_sizes, int n_in,
                              void* d_out, int out_size)
{
    const float* x    = (const float*)d_in[0];
    const float* ctx  = (const float*)d_in[1];
    const float* Wq   = (const float*)d_in[2];
    const float* bq   = (const float*)d_in[3];
    const float* Wk   = (const float*)d_in[4];
    const float* bk   = (const float*)d_in[5];
    const float* Wv   = (const float*)d_in[6];
    const float* bv   = (const float*)d_in[7];
    const float* Wo   = (const float*)d_in[8];
    const float* bo   = (const float*)d_in[9];
    const float* ln_g = (const float*)d_in[10];
    const float* ln_b = (const float*)d_in[11];
    float* out = (float*)d_out;

    float *p_xn, *p_q, *p_k, *p_v, *p_attn;
    unsigned *p_wq, *p_wk, *p_wv, *p_wo;
    cudaGetSymbolAddress((void**)&p_xn,   g_xn);
    cudaGetSymbolAddress((void**)&p_q,    g_q);
    cudaGetSymbolAddress((void**)&p_k,    g_k);
    cudaGetSymbolAddress((void**)&p_v,    g_v);
    cudaGetSymbolAddress((void**)&p_attn, g_attn);
    cudaGetSymbolAddress((void**)&p_wq,   g_wq);
    cudaGetSymbolAddress((void**)&p_wk,   g_wk);
    cudaGetSymbolAddress((void**)&p_wv,   g_wv);
    cudaGetSymbolAddress((void**)&p_wo,   g_wo);

    // 1. quantization scales + ternary encode
    absmean_partial<<<dim3(256, 4), 256>>>(Wq, Wk, Wv, Wo);
    absmean_final<<<4, 256>>>();
    quantize_w<<<dim3(1024, 4), 256>>>(Wq, Wk, Wv, Wo);

    // 2. layernorm
    layernorm_k<<<MQ, 256>>>(x, ln_g, ln_b);

    // 3. projections (tensor cores)
    gemm_tf32<<<dim3(CD / 128, MQ  / 128), 256>>>(p_xn, p_wq, bq, nullptr, p_q, 0);
    gemm_tf32<<<dim3(CD / 128, MKV / 128), 256>>>(ctx,  p_wk, bk, nullptr, p_k, 1);
    gemm_tf32<<<dim3(CD / 128, MKV / 128), 256>>>(ctx,  p_wv, bv, nullptr, p_v, 2);

    // 4. attention (tensor cores)
    size_t att_smem = (size_t)(3 * 64 * ALD + 64 * VLD + 3 * 64) * sizeof(float);
    cudaFuncSetAttribute(attention_tf32, cudaFuncAttributeMaxDynamicSharedMemorySize,
                         (int)att_smem);
    attention_tf32<<<dim3(TQ / 64, CB * NH), 256, att_smem>>>();

    // 5. output projection + bias + residual
    gemm_tf32<<<dim3(CD / 128, MQ / 128), 256>>>(p_attn, p_wo, bo, x, out, 3);
}

// round 8
// speedup vs baseline: 4.3381x; 1.6416x over previous
#include <cuda_runtime.h>
#include <cuda_bf16.h>
#include <math.h>

// Problem constants
#define CB    4
#define TQ    1024
#define TCX   2048
#define CD    1024
#define NH    16
#define HD    64
#define MQ    (CB*TQ)    // 4096
#define MKV   (CB*TCX)   // 8192
#define ATT_SCALE 0.125f
#define LN_EPS 1e-5f
#define Q_EPS  1e-5f

typedef __nv_bfloat16  bf16;
typedef __nv_bfloat162 bf162;

// ---------------- device scratch ----------------
__device__ bf16  g_xn [MQ*CD];
__device__ bf16  g_ctx[MKV*CD];
__device__ bf16  g_qm [MQ*CD];
__device__ bf16  g_km [MKV*CD];
__device__ bf16  g_vm [MKV*CD];
__device__ bf16  g_attn[MQ*CD];
__device__ bf16  g_wq[CD*CD];
__device__ bf16  g_wk[CD*CD];
__device__ bf16  g_wv[CD*CD];
__device__ bf16  g_wo[CD*CD];
__device__ float g_partial[4][256];
__device__ float g_gamma[4];

// ---------------- helpers ----------------
__device__ __forceinline__ void mma_bf16(
    float& c0, float& c1, float& c2, float& c3,
    unsigned a0, unsigned a1, unsigned a2, unsigned a3,
    unsigned b0, unsigned b1)
{
    asm("mma.sync.aligned.m16n8k16.row.col.f32.bf16.bf16.f32 "
        "{%0,%1,%2,%3},{%4,%5,%6,%7},{%8,%9},{%0,%1,%2,%3};"
        : "+f"(c0), "+f"(c1), "+f"(c2), "+f"(c3)
        : "r"(a0), "r"(a1), "r"(a2), "r"(a3), "r"(b0), "r"(b1));
}

__device__ __forceinline__ void cp16(unsigned s, const void* g) {
    asm volatile("cp.async.cg.shared.global [%0], [%1], 16;" :: "r"(s), "l"(g));
}
#define CP_COMMIT  asm volatile("cp.async.commit_group;" ::: "memory")
#define CP_WAIT(N) asm volatile("cp.async.wait_group %0;" :: "n"(N) : "memory")

// ---------------- |W| mean (deterministic two-pass) ----------------
__global__ __launch_bounds__(256) void absmean_partial(
    const float* __restrict__ W0, const float* __restrict__ W1,
    const float* __restrict__ W2, const float* __restrict__ W3)
{
    const float* W = (blockIdx.y == 0) ? W0 : (blockIdx.y == 1) ? W1
                   : (blockIdx.y == 2) ? W2 : W3;
    __shared__ float sh[256];
    int base = blockIdx.x * 4096;
    float acc = 0.f;
    for (int i = threadIdx.x; i < 4096; i += 256)
        acc += fabsf(W[base + i]);
    sh[threadIdx.x] = acc;
    __syncthreads();
    for (int o = 128; o > 0; o >>= 1) {
        if (threadIdx.x < o) sh[threadIdx.x] += sh[threadIdx.x + o];
        __syncthreads();
    }
    if (threadIdx.x == 0) g_partial[blockIdx.y][blockIdx.x] = sh[0];
}

__global__ __launch_bounds__(256) void absmean_final()
{
    __shared__ float sh[256];
    sh[threadIdx.x] = g_partial[blockIdx.x][threadIdx.x];
    __syncthreads();
    for (int o = 128; o > 0; o >>= 1) {
        if (threadIdx.x < o) sh[threadIdx.x] += sh[threadIdx.x + o];
        __syncthreads();
    }
    if (threadIdx.x == 0)
        g_gamma[blockIdx.x] = sh[0] / (float)(CD * CD);
}

// ---------------- ternary quantization (ternary is EXACT in bf16) ----------------
__global__ __launch_bounds__(256) void quantize_w(
    const float* __restrict__ W0, const float* __restrict__ W1,
    const float* __restrict__ W2, const float* __restrict__ W3)
{
    int w = blockIdx.y;
    const float* W = (w == 0) ? W0 : (w == 1) ? W1 : (w == 2) ? W2 : W3;
    bf16* Wd = (w == 0) ? g_wq : (w == 1) ? g_wk : (w == 2) ? g_wv : g_wo;
    float g  = g_gamma[w];
    float gd = g + Q_EPS;
    int idx0 = blockIdx.x * 256 + threadIdx.x;
    #pragma unroll
    for (int r = 0; r < 4; r++) {
        int i = idx0 + r * 262144;
        float t = rintf(W[i] / gd);              // round-half-even, matches jnp
        t = fminf(fmaxf(t, -1.f), 1.f);
        Wd[i] = __float2bfloat16(t);             // {-1,0,1}: exact
    }
}

// ---------------- layernorm (fp32 math, bf16 out) ----------------
__global__ __launch_bounds__(256) void layernorm_k(
    const float* __restrict__ x, const float* __restrict__ gamma,
    const float* __restrict__ beta)
{
    int row = blockIdx.x;
    const float* xr = x + (size_t)row * CD;
    __shared__ float s1[256], s2[256];
    float a = 0.f, b = 0.f;
    for (int i = threadIdx.x; i < CD; i += 256) {
        float v = xr[i];
        a += v; b += v * v;
    }
    s1[threadIdx.x] = a; s2[threadIdx.x] = b;
    __syncthreads();
    for (int o = 128; o > 0; o >>= 1) {
        if (threadIdx.x < o) {
            s1[threadIdx.x] += s1[threadIdx.x + o];
            s2[threadIdx.x] += s2[threadIdx.x + o];
        }
        __syncthreads();
    }
    float mu  = s1[0] / (float)CD;
    float var = s2[0] / (float)CD - mu * mu;
    float rstd = rsqrtf(var + LN_EPS);
    for (int i = threadIdx.x; i < CD; i += 256)
        g_xn[(size_t)row * CD + i] =
            __float2bfloat16((xr[i] - mu) * rstd * gamma[i] + beta[i]);
}

// ---------------- context fp32 -> bf16 ----------------
__global__ __launch_bounds__(256) void convert_ctx(const float* __restrict__ c)
{
    size_t i = (size_t)(blockIdx.x * 256 + threadIdx.x) * 4;
    float4 v = *(const float4*)&c[i];
    bf162* o = (bf162*)&g_ctx[i];
    o[0] = __floats2bfloat162_rn(v.x, v.y);
    o[1] = __floats2bfloat162_rn(v.z, v.w);
}

// ---------------- bf16 tensor-core NT GEMM, cp.async double-buffered ----------------
// out[M,1024] = (A[M,1024] @ Wt[1024,1024]^T)*gamma + bias (+resid)
// BM=BN=128, BK=32, 8 warps (2x4), warp tile 64x32, m16n8k16.
#define GLDW 20   // smem words per row: 16 data + 4 pad (conflict-free frags, 16B-aligned chunks)

template<int BF16OUT>
__global__ __launch_bounds__(256) void gemm_bf16k(
    const bf16* __restrict__ A, const bf16* __restrict__ W,
    const float* __restrict__ bias, const float* __restrict__ resid,
    void* __restrict__ outp, int gidx)
{
    __shared__ unsigned As[2][128 * GLDW];
    __shared__ unsigned Ws[2][128 * GLDW];

    const int tid = threadIdx.x, lane = tid & 31, wid = tid >> 5;
    const int bm = blockIdx.y * 128, bn = blockIdx.x * 128;
    const int wm = (wid >> 2) * 64, wn = (wid & 3) * 32;
    const int lr4 = lane >> 2, lc4 = lane & 3;

    const unsigned sA = (unsigned)__cvta_generic_to_shared(&As[0][0]);
    const unsigned sW = (unsigned)__cvta_generic_to_shared(&Ws[0][0]);

    const int lrow = tid >> 2;          // 0..63
    const int lko  = (tid & 3) * 8;     // bf16 offset in K
    const unsigned soff0 = (unsigned)(lrow * GLDW + (tid & 3) * 4) * 4;
    const unsigned soff1 = (unsigned)((lrow + 64) * GLDW + (tid & 3) * 4) * 4;

    float c[4][4][4];
    #pragma unroll
    for (int i = 0; i < 4; i++)
        #pragma unroll
        for (int j = 0; j < 4; j++)
            #pragma unroll
            for (int r = 0; r < 4; r++) c[i][j][r] = 0.f;

    // prologue: tile 0 -> buf 0
    {
        const bf16* ga = A + (size_t)(bm + lrow) * CD + lko;
        const bf16* gw = W + (size_t)(bn + lrow) * CD + lko;
        cp16(sA + soff0, ga);
        cp16(sW + soff0, gw);
        cp16(sA + soff1, ga + (size_t)64 * CD);
        cp16(sW + soff1, gw + (size_t)64 * CD);
    }
    CP_COMMIT;

    for (int kt = 0; kt < CD / 32; kt++) {
        const int cur = kt & 1;
        if (kt + 1 < CD / 32) {
            const int k0 = (kt + 1) * 32;
            const unsigned bofs = (unsigned)((cur ^ 1) * 128 * GLDW * 4);
            const bf16* ga = A + (size_t)(bm + lrow) * CD + k0 + lko;
            const bf16* gw = W + (size_t)(bn + lrow) * CD + k0 + lko;
            cp16(sA + bofs + soff0, ga);
            cp16(sW + bofs + soff0, gw);
            cp16(sA + bofs + soff1, ga + (size_t)64 * CD);
            cp16(sW + bofs + soff1, gw + (size_t)64 * CD);
            CP_COMMIT;
            CP_WAIT(1);
        } else {
            CP_WAIT(0);
        }
        __syncthreads();

        const unsigned* Ab = &As[cur][0];
        const unsigned* Wb = &Ws[cur][0];
        #pragma unroll
        for (int ks = 0; ks < 2; ks++) {
            unsigned a[4][4], b[4][2];
            #pragma unroll
            for (int i = 0; i < 4; i++) {
                int r = wm + i * 16 + lr4;
                const unsigned* p0 = &Ab[r * GLDW + ks * 8 + lc4];
                const unsigned* p1 = &Ab[(r + 8) * GLDW + ks * 8 + lc4];
                a[i][0] = p0[0]; a[i][1] = p1[0]; a[i][2] = p0[4]; a[i][3] = p1[4];
            }
            #pragma unroll
            for (int j = 0; j < 4; j++) {
                const unsigned* p = &Wb[(wn + j * 8 + lr4) * GLDW + ks * 8 + lc4];
                b[j][0] = p[0]; b[j][1] = p[4];
            }
            #pragma unroll
            for (int i = 0; i < 4; i++)
                #pragma unroll
                for (int j = 0; j < 4; j++)
                    mma_bf16(c[i][j][0], c[i][j][1], c[i][j][2], c[i][j][3],
                             a[i][0], a[i][1], a[i][2], a[i][3],
                             b[j][0], b[j][1]);
        }
        __syncthreads();
    }

    const float g = g_gamma[gidx];
    #pragma unroll
    for (int i = 0; i < 4; i++) {
        int r0 = bm + wm + i * 16 + lr4;
        #pragma unroll
        for (int j = 0; j < 4; j++) {
            int col = bn + wn + j * 8 + lc4 * 2;
            float b0v = bias[col], b1v = bias[col + 1];
            size_t i00 = (size_t)r0 * CD + col;
            size_t i10 = (size_t)(r0 + 8) * CD + col;
            float v00 = c[i][j][0] * g + b0v;
            float v01 = c[i][j][1] * g + b1v;
            float v10 = c[i][j][2] * g + b0v;
            float v11 = c[i][j][3] * g + b1v;
            if (BF16OUT) {
                bf162* ob = (bf162*)outp;
                ob[i00 >> 1] = __floats2bfloat162_rn(v00, v01);
                ob[i10 >> 1] = __floats2bfloat162_rn(v10, v11);
            } else {
                float* of = (float*)outp;
                of[i00]     = v00 + resid[i00];
                of[i00 + 1] = v01 + resid[i00 + 1];
                of[i10]     = v10 + resid[i10];
                of[i10 + 1] = v11 + resid[i10 + 1];
            }
        }
    }
}

// ---------------- flash attention, bf16 tensor cores ----------------
// 64 q-rows/block, 64-wide kv tiles, fp32 online softmax.
// 8 warps: 4(m-groups of 16 q) x 2(col halves of 32).
#define LQW 36   // word stride for Q/K/P (72 bf16) and Vp (32+4 pad words)
#define LSS 66   // fp32 word stride for scores

__global__ __launch_bounds__(256) void attention_bf16()
{
    extern __shared__ unsigned usm[];
    unsigned* Qu = usm;                    // 64*LQW
    unsigned* Ku = Qu + 64 * LQW;
    unsigned* Pu = Ku + 64 * LQW;
    unsigned* Vp = Pu + 64 * LQW;          // pair-packed: word[d][kv2] = {V[2kv2][d], V[2kv2+1][d]}
    float* Ss  = (float*)(Vp + 64 * LQW);  // 64*LSS fp32 scores
    float* m_s = Ss + 64 * LSS;
    float* l_s = m_s + 64;
    float* c_s = l_s + 64;

    const int tid = threadIdx.x, lane = tid & 31, wid = tid >> 5;
    const int qblk = blockIdx.x, bh = blockIdx.y;
    const int b = bh >> 4, h = bh & 15;
    const int lr4 = lane >> 2, lc4 = lane & 3;
    const int wr = (wid >> 1) * 16;
    const int wd = (wid & 1) * 32;

    const bf16* Qb = g_qm + ((size_t)(b * TQ + qblk * 64)) * CD + h * HD;
    const bf16* Kb = g_km + ((size_t)(b * TCX)) * CD + h * HD;
    const bf16* Vb = g_vm + ((size_t)(b * TCX)) * CD + h * HD;

    // Q load, fold 1/8 scale (exact power of two in bf16)
    const bf162 sc2 = __floats2bfloat162_rn(ATT_SCALE, ATT_SCALE);
    #pragma unroll
    for (int it = 0; it < 2; it++) {
        int i = tid + it * 256;
        int row = i >> 3, d0 = (i & 7) * 8;
        uint4 v = *(const uint4*)(Qb + (size_t)row * CD + d0);
        bf162* pv = (bf162*)&v;
        #pragma unroll
        for (int m = 0; m < 4; m++) pv[m] = __hmul2(pv[m], sc2);
        *(uint4*)&Qu[row * LQW + (i & 7) * 4] = v;
    }
    if (tid < 64) { m_s[tid] = -1e30f; l_s[tid] = 0.f; }

    float o[4][4];
    #pragma unroll
    for (int j = 0; j < 4; j++)
        #pragma unroll
        for (int r = 0; r < 4; r++) o[j][r] = 0.f;

    for (int t = 0; t < TCX / 64; t++) {
        __syncthreads();   // prev iter done reading Ku/Vp/Pu; Qs ready on t=0
        // K tile
        #pragma unroll
        for (int it = 0; it < 2; it++) {
            int i = tid + it * 256;
            int row = i >> 3, d0 = (i & 7) * 8;
            uint4 v = *(const uint4*)(Kb + (size_t)(t * 64 + row) * CD + d0);
            *(uint4*)&Ku[row * LQW + (i & 7) * 4] = v;
        }
        // V tile, pair-packed (conflict-free stores: bank = 4*(d0+m)+kv2)
        {
            int kv2 = tid & 31, d0 = (tid >> 5) * 8;
            const bf16* vp = Vb + (size_t)(t * 64 + 2 * kv2) * CD + d0;
            uint4 r0 = *(const uint4*)vp;
            uint4 r1 = *(const uint4*)(vp + CD);
            unsigned ra[4] = {r0.x, r0.y, r0.z, r0.w};
            unsigned rb[4] = {r1.x, r1.y, r1.z, r1.w};
            #pragma unroll
            for (int m = 0; m < 8; m++) {
                unsigned w = __byte_perm(ra[m >> 1], rb[m >> 1],
                                         (m & 1) ? 0x7632 : 0x5410);
                Vp[(d0 + m) * LQW + kv2] = w;
            }
        }
        __syncthreads();

        // S = Q K^T
        float s[4][4];
        #pragma unroll
        for (int j = 0; j < 4; j++)
            #pragma unroll
            for (int r = 0; r < 4; r++) s[j][r] = 0.f;
        #pragma unroll
        for (int ks = 0; ks < 4; ks++) {
            const unsigned* q0 = &Qu[(wr + lr4) * LQW + ks * 8 + lc4];
            const unsigned* q1 = &Qu[(wr + lr4 + 8) * LQW + ks * 8 + lc4];
            unsigned a0 = q0[0], a1 = q1[0], a2 = q0[4], a3 = q1[4];
            #pragma unroll
            for (int j = 0; j < 4; j++) {
                const unsigned* kp = &Ku[(wd + j * 8 + lr4) * LQW + ks * 8 + lc4];
                mma_bf16(s[j][0], s[j][1], s[j][2], s[j][3],
                         a0, a1, a2, a3, kp[0], kp[4]);
            }
        }
        #pragma unroll
        for (int j = 0; j < 4; j++) {
            int colb = wd + j * 8 + lc4 * 2;
            *(float2*)&Ss[(wr + lr4) * LSS + colb]     = make_float2(s[j][0], s[j][1]);
            *(float2*)&Ss[(wr + lr4 + 8) * LSS + colb] = make_float2(s[j][2], s[j][3]);
        }
        __syncthreads();

        // online softmax: 4 threads/row, shfl combine; probs -> bf16 Pu
        {
            int row = tid >> 2, part = tid & 3;
            float* Sr = Ss + row * LSS + part * 16;
            float mt = -1e30f;
            #pragma unroll
            for (int cc = 0; cc < 16; cc++) mt = fmaxf(mt, Sr[cc]);
            mt = fmaxf(mt, __shfl_xor_sync(0xffffffffu, mt, 1));
            mt = fmaxf(mt, __shfl_xor_sync(0xffffffffu, mt, 2));
            float mo = m_s[row];
            float mn = fmaxf(mo, mt);
            float p[16], ls = 0.f;
            #pragma unroll
            for (int cc = 0; cc < 16; cc++) {
                p[cc] = __expf(Sr[cc] - mn);
                ls += p[cc];
            }
            unsigned* Pr = &Pu[row * LQW + part * 8];
            #pragma unroll
            for (int wx = 0; wx < 8; wx++) {
                bf162 pk = __floats2bfloat162_rn(p[2 * wx], p[2 * wx + 1]);
                Pr[wx] = *(unsigned*)&pk;
            }
            ls += __shfl_xor_sync(0xffffffffu, ls, 1);
            ls += __shfl_xor_sync(0xffffffffu, ls, 2);
            if (part == 0) {
                float cr = __expf(mo - mn);
                c_s[row] = cr;
                l_s[row] = l_s[row] * cr + ls;
                m_s[row] = mn;
            }
        }
        __syncthreads();

        // rescale running O
        float cr0 = c_s[wr + lr4];
        float cr1 = c_s[wr + lr4 + 8];
        #pragma unroll
        for (int j = 0; j < 4; j++) {
            o[j][0] *= cr0; o[j][1] *= cr0;
            o[j][2] *= cr1; o[j][3] *= cr1;
        }

        // O += P @ V
        #pragma unroll
        for (int ks = 0; ks < 4; ks++) {
            const unsigned* p0 = &Pu[(wr + lr4) * LQW + ks * 8 + lc4];
            const unsigned* p1 = &Pu[(wr + lr4 + 8) * LQW + ks * 8 + lc4];
            unsigned a0 = p0[0], a1 = p1[0], a2 = p0[4], a3 = p1[4];
            #pragma unroll
            for (int j = 0; j < 4; j++) {
                const unsigned* vb2 = &Vp[(wd + j * 8 + lr4) * LQW + ks * 8 + lc4];
                mma_bf16(o[j][0], o[j][1], o[j][2], o[j][3],
                         a0, a1, a2, a3, vb2[0], vb2[4]);
            }
        }
    }

    // epilogue: normalize, write bf16
    float inv0 = 1.f / l_s[wr + lr4];
    float inv1 = 1.f / l_s[wr + lr4 + 8];
    bf16* Ob = g_attn + ((size_t)(b * TQ + qblk * 64)) * CD + h * HD;
    #pragma unroll
    for (int j = 0; j < 4; j++) {
        int col = wd + j * 8 + lc4 * 2;
        *(bf162*)(Ob + (size_t)(wr + lr4) * CD + col) =
            __floats2bfloat162_rn(o[j][0] * inv0, o[j][1] * inv0);
        *(bf162*)(Ob + (size_t)(wr + lr4 + 8) * CD + col) =
            __floats2bfloat162_rn(o[j][2] * inv1, o[j][3] * inv1);
    }
}

// ---------------- host launch ----------------
extern "C" void kernel_launch(void* const* d_in, const int* in_sizes, int n_in,
                              void* d_out, int out_size)
{
    const float* x    = (const float*)d_in[0];
    const float* ctx  = (const float*)d_in[1];
    const float* Wq   = (const float*)d_in[2];
    const float* bq   = (const float*)d_in[3];
    const float* Wk   = (const float*)d_in[4];
    const float* bk   = (const float*)d_in[5];
    const float* Wv   = (const float*)d_in[6];
    const float* bv   = (const float*)d_in[7];
    const float* Wo   = (const float*)d_in[8];
    const float* bo   = (const float*)d_in[9];
    const float* ln_g = (const float*)d_in[10];
    const float* ln_b = (const float*)d_in[11];
    float* out = (float*)d_out;

    bf16 *p_xn, *p_ctx, *p_q, *p_k, *p_v, *p_attn;
    bf16 *p_wq, *p_wk, *p_wv, *p_wo;
    cudaGetSymbolAddress((void**)&p_xn,   g_xn);
    cudaGetSymbolAddress((void**)&p_ctx,  g_ctx);
    cudaGetSymbolAddress((void**)&p_q,    g_qm);
    cudaGetSymbolAddress((void**)&p_k,    g_km);
    cudaGetSymbolAddress((void**)&p_v,    g_vm);
    cudaGetSymbolAddress((void**)&p_attn, g_attn);
    cudaGetSymbolAddress((void**)&p_wq,   g_wq);
    cudaGetSymbolAddress((void**)&p_wk,   g_wk);
    cudaGetSymbolAddress((void**)&p_wv,   g_wv);
    cudaGetSymbolAddress((void**)&p_wo,   g_wo);

    // 1. quantization scales + ternary bf16 encode
    absmean_partial<<<dim3(256, 4), 256>>>(Wq, Wk, Wv, Wo);
    absmean_final<<<4, 256>>>();
    quantize_w<<<dim3(1024, 4), 256>>>(Wq, Wk, Wv, Wo);

    // 2. layernorm (bf16 out) + context convert
    layernorm_k<<<MQ, 256>>>(x, ln_g, ln_b);
    convert_ctx<<<(MKV * CD) / 1024, 256>>>(ctx);

    // 3. projections (bf16 tensor cores, cp.async double-buffered)
    gemm_bf16k<1><<<dim3(CD / 128, MQ  / 128), 256>>>(p_xn,  p_wq, bq, nullptr, p_q, 0);
    gemm_bf16k<1><<<dim3(CD / 128, MKV / 128), 256>>>(p_ctx, p_wk, bk, nullptr, p_k, 1);
    gemm_bf16k<1><<<dim3(CD / 128, MKV / 128), 256>>>(p_ctx, p_wv, bv, nullptr, p_v, 2);

    // 4. attention
    size_t att_smem = (size_t)(4 * 64 * LQW + 64 * LSS + 3 * 64) * 4;
    cudaFuncSetAttribute(attention_bf16,
                         cudaFuncAttributeMaxDynamicSharedMemorySize, (int)att_smem);
    attention_bf16<<<dim3(TQ / 64, CB * NH), 256, att_smem>>>();

    // 5. output projection + bias + residual (fp32 out)
    gemm_bf16k<0><<<dim3(CD / 128, MQ / 128), 256>>>(p_attn, p_wo, bo, x, out, 3);
}

// round 10
// speedup vs baseline: 5.8917x; 1.3581x over previous
#include <cuda_runtime.h>
#include <cuda_bf16.h>
#include <math.h>

// Problem constants
#define CB    4
#define TQ    1024
#define TCX   2048
#define CD    1024
#define NH    16
#define HD    64
#define MQ    (CB*TQ)    // 4096
#define MKV   (CB*TCX)   // 8192
#define ATT_SCALE 0.125f
#define LN_EPS 1e-5f
#define Q_EPS  1e-5f

typedef __nv_bfloat16  bf16;
typedef __nv_bfloat162 bf162;

// ---------------- device scratch ----------------
__device__ bf16  g_xn [MQ*CD];
__device__ bf16  g_ctx[MKV*CD];
__device__ bf16  g_qm [MQ*CD];
__device__ bf16  g_km [MKV*CD];
__device__ bf16  g_vm [MKV*CD];
__device__ bf16  g_attn[MQ*CD];
__device__ bf16  g_wq[CD*CD];
__device__ bf16  g_wk[CD*CD];
__device__ bf16  g_wv[CD*CD];
__device__ bf16  g_wo[CD*CD];
__device__ float g_partial[4][256];
__device__ float g_gamma[4];

// ---------------- helpers ----------------
__device__ __forceinline__ void mma_bf16(
    float& c0, float& c1, float& c2, float& c3,
    unsigned a0, unsigned a1, unsigned a2, unsigned a3,
    unsigned b0, unsigned b1)
{
    asm("mma.sync.aligned.m16n8k16.row.col.f32.bf16.bf16.f32 "
        "{%0,%1,%2,%3},{%4,%5,%6,%7},{%8,%9},{%0,%1,%2,%3};"
        : "+f"(c0), "+f"(c1), "+f"(c2), "+f"(c3)
        : "r"(a0), "r"(a1), "r"(a2), "r"(a3), "r"(b0), "r"(b1));
}

__device__ __forceinline__ void ldsm_x4(
    unsigned& r0, unsigned& r1, unsigned& r2, unsigned& r3, unsigned addr)
{
    asm volatile("ldmatrix.sync.aligned.m8n8.x4.shared.b16 {%0,%1,%2,%3}, [%4];"
        : "=r"(r0), "=r"(r1), "=r"(r2), "=r"(r3) : "r"(addr));
}

__device__ __forceinline__ void ldsm_x4_t(
    unsigned& r0, unsigned& r1, unsigned& r2, unsigned& r3, unsigned addr)
{
    asm volatile("ldmatrix.sync.aligned.m8n8.x4.trans.shared.b16 {%0,%1,%2,%3}, [%4];"
        : "=r"(r0), "=r"(r1), "=r"(r2), "=r"(r3) : "r"(addr));
}

__device__ __forceinline__ void cp16(unsigned s, const void* g) {
    asm volatile("cp.async.cg.shared.global [%0], [%1], 16;" :: "r"(s), "l"(g));
}
#define CP_COMMIT  asm volatile("cp.async.commit_group;" ::: "memory")
#define CP_WAIT(N) asm volatile("cp.async.wait_group %0;" :: "n"(N) : "memory")

__device__ __forceinline__ unsigned packbf(float a, float b) {
    bf162 t = __floats2bfloat162_rn(a, b);
    return *(unsigned*)&t;
}

// ---------------- |W| mean (deterministic two-pass) ----------------
__global__ __launch_bounds__(256) void absmean_partial(
    const float* __restrict__ W0, const float* __restrict__ W1,
    const float* __restrict__ W2, const float* __restrict__ W3)
{
    const float* W = (blockIdx.y == 0) ? W0 : (blockIdx.y == 1) ? W1
                   : (blockIdx.y == 2) ? W2 : W3;
    __shared__ float sh[256];
    int base = blockIdx.x * 4096;
    float acc = 0.f;
    for (int i = threadIdx.x; i < 4096; i += 256)
        acc += fabsf(W[base + i]);
    sh[threadIdx.x] = acc;
    __syncthreads();
    for (int o = 128; o > 0; o >>= 1) {
        if (threadIdx.x < o) sh[threadIdx.x] += sh[threadIdx.x + o];
        __syncthreads();
    }
    if (threadIdx.x == 0) g_partial[blockIdx.y][blockIdx.x] = sh[0];
}

__global__ __launch_bounds__(256) void absmean_final()
{
    __shared__ float sh[256];
    sh[threadIdx.x] = g_partial[blockIdx.x][threadIdx.x];
    __syncthreads();
    for (int o = 128; o > 0; o >>= 1) {
        if (threadIdx.x < o) sh[threadIdx.x] += sh[threadIdx.x + o];
        __syncthreads();
    }
    if (threadIdx.x == 0)
        g_gamma[blockIdx.x] = sh[0] / (float)(CD * CD);
}

// ---------------- ternary quantization (ternary EXACT in bf16) ----------------
__global__ __launch_bounds__(256) void quantize_w(
    const float* __restrict__ W0, const float* __restrict__ W1,
    const float* __restrict__ W2, const float* __restrict__ W3)
{
    int w = blockIdx.y;
    const float* W = (w == 0) ? W0 : (w == 1) ? W1 : (w == 2) ? W2 : W3;
    bf16* Wd = (w == 0) ? g_wq : (w == 1) ? g_wk : (w == 2) ? g_wv : g_wo;
    float g  = g_gamma[w];
    float gd = g + Q_EPS;
    int idx0 = blockIdx.x * 256 + threadIdx.x;
    #pragma unroll
    for (int r = 0; r < 4; r++) {
        int i = idx0 + r * 262144;
        float t = rintf(W[i] / gd);
        t = fminf(fmaxf(t, -1.f), 1.f);
        Wd[i] = __float2bfloat16(t);
    }
}

// ---------------- layernorm: warp per row ----------------
__global__ __launch_bounds__(256) void layernorm_k(
    const float* __restrict__ x, const float* __restrict__ gamma,
    const float* __restrict__ beta)
{
    int row = blockIdx.x * 8 + (threadIdx.x >> 5);
    int lane = threadIdx.x & 31;
    const float4* xr = (const float4*)(x + (size_t)row * CD);
    float4 v[8];
    float a = 0.f, b2 = 0.f;
    #pragma unroll
    for (int i = 0; i < 8; i++) {
        v[i] = xr[lane + i * 32];
        a  += v[i].x + v[i].y + v[i].z + v[i].w;
        b2 += v[i].x * v[i].x + v[i].y * v[i].y + v[i].z * v[i].z + v[i].w * v[i].w;
    }
    #pragma unroll
    for (int o = 16; o > 0; o >>= 1) {
        a  += __shfl_xor_sync(0xffffffffu, a, o);
        b2 += __shfl_xor_sync(0xffffffffu, b2, o);
    }
    float mu = a / (float)CD;
    float var = b2 / (float)CD - mu * mu;
    float rstd = rsqrtf(var + LN_EPS);
    uint2* orow = (uint2*)(g_xn + (size_t)row * CD);
    const float4* gm = (const float4*)gamma;
    const float4* bt = (const float4*)beta;
    #pragma unroll
    for (int i = 0; i < 8; i++) {
        float4 g4 = gm[lane + i * 32];
        float4 b4 = bt[lane + i * 32];
        float y0 = (v[i].x - mu) * rstd * g4.x + b4.x;
        float y1 = (v[i].y - mu) * rstd * g4.y + b4.y;
        float y2 = (v[i].z - mu) * rstd * g4.z + b4.z;
        float y3 = (v[i].w - mu) * rstd * g4.w + b4.w;
        uint2 w;
        w.x = packbf(y0, y1);
        w.y = packbf(y2, y3);
        orow[lane + i * 32] = w;
    }
}

// ---------------- context fp32 -> bf16 ----------------
__global__ __launch_bounds__(256) void convert_ctx(const float* __restrict__ c)
{
    size_t i = (size_t)(blockIdx.x * 256 + threadIdx.x) * 4;
    float4 v = *(const float4*)&c[i];
    bf162* o = (bf162*)&g_ctx[i];
    o[0] = __floats2bfloat162_rn(v.x, v.y);
    o[1] = __floats2bfloat162_rn(v.z, v.w);
}

// ---------------- bf16 tensor-core NT GEMM: cp.async + ldmatrix ----------------
// BM=BN=128, BK=32, 8 warps (2x4), warp tile 64x32, m16n8k16.
#define GLDW 20

template<int BF16OUT>
__global__ __launch_bounds__(256) void gemm_bf16k(
    const bf16* __restrict__ A, const bf16* __restrict__ W,
    const float* __restrict__ bias, const float* __restrict__ resid,
    void* __restrict__ outp, int gidx)
{
    __shared__ unsigned As[2][128 * GLDW];
    __shared__ unsigned Ws[2][128 * GLDW];

    const int tid = threadIdx.x, lane = tid & 31, wid = tid >> 5;
    const int bm = blockIdx.y * 128, bn = blockIdx.x * 128;
    const int wm = (wid >> 2) * 64, wn = (wid & 3) * 32;
    const int lr4 = lane >> 2, lc4 = lane & 3;
    const int g8 = lane >> 3, r8 = lane & 7;

    const unsigned sA = (unsigned)__cvta_generic_to_shared(&As[0][0]);
    const unsigned sW = (unsigned)__cvta_generic_to_shared(&Ws[0][0]);

    const int lrow = tid >> 2;
    const int lko  = (tid & 3) * 8;
    const unsigned soff0 = (unsigned)(lrow * GLDW + (tid & 3) * 4) * 4;
    const unsigned soff1 = (unsigned)((lrow + 64) * GLDW + (tid & 3) * 4) * 4;

    // ldmatrix lane offsets (word units, before *4)
    const int arow = ((g8 & 1) ? 8 : 0) + r8;      // + wm + i*16
    const int acol = (g8 >= 2) ? 4 : 0;            // + ks*8
    const int brow = ((g8 >= 2) ? 8 : 0) + r8;     // + wn + jp*16
    const int bcol = (g8 & 1) ? 4 : 0;             // + ks*8

    float c[4][4][4];
    #pragma unroll
    for (int i = 0; i < 4; i++)
        #pragma unroll
        for (int j = 0; j < 4; j++)
            #pragma unroll
            for (int r = 0; r < 4; r++) c[i][j][r] = 0.f;

    {
        const bf16* ga = A + (size_t)(bm + lrow) * CD + lko;
        const bf16* gw = W + (size_t)(bn + lrow) * CD + lko;
        cp16(sA + soff0, ga);
        cp16(sW + soff0, gw);
        cp16(sA + soff1, ga + (size_t)64 * CD);
        cp16(sW + soff1, gw + (size_t)64 * CD);
    }
    CP_COMMIT;

    for (int kt = 0; kt < CD / 32; kt++) {
        const int cur = kt & 1;
        if (kt + 1 < CD / 32) {
            const int k0 = (kt + 1) * 32;
            const unsigned bofs = (unsigned)((cur ^ 1) * 128 * GLDW * 4);
            const bf16* ga = A + (size_t)(bm + lrow) * CD + k0 + lko;
            const bf16* gw = W + (size_t)(bn + lrow) * CD + k0 + lko;
            cp16(sA + bofs + soff0, ga);
            cp16(sW + bofs + soff0, gw);
            cp16(sA + bofs + soff1, ga + (size_t)64 * CD);
            cp16(sW + bofs + soff1, gw + (size_t)64 * CD);
            CP_COMMIT;
            CP_WAIT(1);
        } else {
            CP_WAIT(0);
        }
        __syncthreads();

        const unsigned bufo = (unsigned)(cur * 128 * GLDW * 4);
        #pragma unroll
        for (int ks = 0; ks < 2; ks++) {
            unsigned a[4][4], b[2][4];
            #pragma unroll
            for (int i = 0; i < 4; i++)
                ldsm_x4(a[i][0], a[i][1], a[i][2], a[i][3],
                        sA + bufo + (unsigned)((wm + i * 16 + arow) * GLDW
                                               + acol + ks * 8) * 4);
            #pragma unroll
            for (int jp = 0; jp < 2; jp++)
                ldsm_x4(b[jp][0], b[jp][1], b[jp][2], b[jp][3],
                        sW + bufo + (unsigned)((wn + jp * 16 + brow) * GLDW
                                               + bcol + ks * 8) * 4);
            #pragma unroll
            for (int i = 0; i < 4; i++)
                #pragma unroll
                for (int jp = 0; jp < 2; jp++) {
                    mma_bf16(c[i][2*jp][0], c[i][2*jp][1], c[i][2*jp][2], c[i][2*jp][3],
                             a[i][0], a[i][1], a[i][2], a[i][3], b[jp][0], b[jp][1]);
                    mma_bf16(c[i][2*jp+1][0], c[i][2*jp+1][1], c[i][2*jp+1][2], c[i][2*jp+1][3],
                             a[i][0], a[i][1], a[i][2], a[i][3], b[jp][2], b[jp][3]);
                }
        }
        __syncthreads();
    }

    const float g = g_gamma[gidx];
    #pragma unroll
    for (int i = 0; i < 4; i++) {
        int r0 = bm + wm + i * 16 + lr4;
        #pragma unroll
        for (int j = 0; j < 4; j++) {
            int col = bn + wn + j * 8 + lc4 * 2;
            float b0v = bias[col], b1v = bias[col + 1];
            size_t i00 = (size_t)r0 * CD + col;
            size_t i10 = (size_t)(r0 + 8) * CD + col;
            float v00 = c[i][j][0] * g + b0v;
            float v01 = c[i][j][1] * g + b1v;
            float v10 = c[i][j][2] * g + b0v;
            float v11 = c[i][j][3] * g + b1v;
            if (BF16OUT) {
                bf162* ob = (bf162*)outp;
                ob[i00 >> 1] = __floats2bfloat162_rn(v00, v01);
                ob[i10 >> 1] = __floats2bfloat162_rn(v10, v11);
            } else {
                float* of = (float*)outp;
                of[i00]     = v00 + resid[i00];
                of[i00 + 1] = v01 + resid[i00 + 1];
                of[i10]     = v10 + resid[i10];
                of[i10 + 1] = v11 + resid[i10 + 1];
            }
        }
    }
}

// ---------------- flash attention: register softmax, cp.async K/V, ldmatrix ----------------
// 64 q-rows/block, kv tiles of 64. 8 warps: 4 row groups x 2 kv-halves.
// Each warp: S(16q x 32kv) in regs -> softmax in regs (1-sync stat exchange)
// -> O_partial(16q x 64d) accumulated over its kv half; pair-sum at end.
#define LKW 36   // K/V/Q smem row stride in words (64 bf16 = 32 + 4 pad)

__global__ __launch_bounds__(256) void attention_bf16()
{
    extern __shared__ unsigned usm[];
    // [0 .. 2*64*LKW) : K double buffer | [2*64*LKW .. 4*64*LKW) : V double buffer
    // [4*64*LKW .. +256) : stats exchange.  Final O-combine aliases usm[0..4096).
    float* ex = (float*)(usm + 4 * 64 * LKW);

    const int tid = threadIdx.x, lane = tid & 31, wid = tid >> 5;
    const int qblk = blockIdx.x, bh = blockIdx.y;
    const int b = bh >> 4, h = bh & 15;
    const int lr4 = lane >> 2, lc4 = lane & 3;
    const int g8 = lane >> 3, r8 = lane & 7;
    const int wr = (wid >> 1) * 16;
    const int wdh = wid & 1;
    const int wd = wdh * 32;

    const bf16* Qb = g_qm + ((size_t)(b * TQ + qblk * 64)) * CD + h * HD;
    const bf16* Kb = g_km + ((size_t)(b * TCX)) * CD + h * HD;
    const bf16* Vb = g_vm + ((size_t)(b * TCX)) * CD + h * HD;

    const unsigned sbase = (unsigned)__cvta_generic_to_shared(usm);
    const unsigned sK0 = sbase;
    const unsigned sV0 = sbase + 2u * 64 * LKW * 4;

    // ---- stage Q (scaled) into K buffer 0, extract A-fragments, then free it
    const bf162 sc2 = __floats2bfloat162_rn(ATT_SCALE, ATT_SCALE);
    #pragma unroll
    for (int it = 0; it < 2; it++) {
        int i = tid + it * 256;
        int row = i >> 3, d0 = (i & 7) * 8;
        uint4 v = *(const uint4*)(Qb + (size_t)row * CD + d0);
        bf162* pv = (bf162*)&v;
        #pragma unroll
        for (int m = 0; m < 4; m++) pv[m] = __hmul2(pv[m], sc2);
        *(uint4*)&usm[row * LKW + (i & 7) * 4] = v;
    }
    __syncthreads();
    unsigned q[4][4];
    {
        int qrow = wr + ((g8 & 1) ? 8 : 0) + r8;
        int qcol = (g8 >= 2) ? 4 : 0;
        #pragma unroll
        for (int ks = 0; ks < 4; ks++)
            ldsm_x4(q[ks][0], q[ks][1], q[ks][2], q[ks][3],
                    sK0 + (unsigned)(qrow * LKW + qcol + ks * 8) * 4);
    }
    __syncthreads();

    // ---- prologue: tile 0 -> buffer 0
    #pragma unroll
    for (int u = 0; u < 2; u++) {
        int cc = tid + u * 256;
        int row = cc >> 3, qc = cc & 7;
        unsigned so = (unsigned)(row * LKW + qc * 4) * 4;
        cp16(sK0 + so, Kb + (size_t)row * CD + qc * 8);
        cp16(sV0 + so, Vb + (size_t)row * CD + qc * 8);
    }
    CP_COMMIT;

    float m0 = -1e30f, m1 = -1e30f, l0 = 0.f, l1 = 0.f;
    float o[8][4];
    #pragma unroll
    for (int j = 0; j < 8; j++)
        #pragma unroll
        for (int r = 0; r < 4; r++) o[j][r] = 0.f;

    // ldmatrix lane offsets
    const int krow = wd + ((g8 >= 2) ? 8 : 0) + r8;   // + jp*16
    const int kcol = (g8 & 1) ? 4 : 0;                // + ks*8
    const int vrow = wd + ((g8 & 1) ? 8 : 0) + r8;    // + ks2*16
    const int vcol = (g8 >= 2) ? 4 : 0;               // + jp*8

    for (int t = 0; t < TCX / 64; t++) {
        const int cur = t & 1;
        const unsigned bo = (unsigned)(cur * 64 * LKW * 4);
        __syncthreads();  // all warps done reading buffer cur^1 (iter t-1)
        if (t + 1 < TCX / 64) {
            const unsigned bn_ = (unsigned)((cur ^ 1) * 64 * LKW * 4);
            #pragma unroll
            for (int u = 0; u < 2; u++) {
                int cc = tid + u * 256;
                int row = cc >> 3, qc = cc & 7;
                unsigned so = bn_ + (unsigned)(row * LKW + qc * 4) * 4;
                cp16(sK0 + so, Kb + (size_t)((t + 1) * 64 + row) * CD + qc * 8);
                cp16(sV0 + so, Vb + (size_t)((t + 1) * 64 + row) * CD + qc * 8);
            }
            CP_COMMIT;
            CP_WAIT(1);
        } else {
            CP_WAIT(0);
        }
        __syncthreads();  // buffer cur visible to all

        // ---- S = Q K^T (regs)
        float s[4][4];
        #pragma unroll
        for (int j = 0; j < 4; j++)
            #pragma unroll
            for (int r = 0; r < 4; r++) s[j][r] = 0.f;
        #pragma unroll
        for (int ks = 0; ks < 4; ks++) {
            #pragma unroll
            for (int jp = 0; jp < 2; jp++) {
                unsigned kb0, kb1, kb2, kb3;
                ldsm_x4(kb0, kb1, kb2, kb3,
                        sK0 + bo + (unsigned)((krow + jp * 16) * LKW + kcol + ks * 8) * 4);
                mma_bf16(s[2*jp][0], s[2*jp][1], s[2*jp][2], s[2*jp][3],
                         q[ks][0], q[ks][1], q[ks][2], q[ks][3], kb0, kb1);
                mma_bf16(s[2*jp+1][0], s[2*jp+1][1], s[2*jp+1][2], s[2*jp+1][3],
                         q[ks][0], q[ks][1], q[ks][2], q[ks][3], kb2, kb3);
            }
        }

        // ---- softmax partials (local to this warp's 32 kv cols)
        float mx0 = -1e30f, mx1 = -1e30f;
        #pragma unroll
        for (int j = 0; j < 4; j++) {
            mx0 = fmaxf(mx0, fmaxf(s[j][0], s[j][1]));
            mx1 = fmaxf(mx1, fmaxf(s[j][2], s[j][3]));
        }
        mx0 = fmaxf(mx0, __shfl_xor_sync(0xffffffffu, mx0, 1));
        mx0 = fmaxf(mx0, __shfl_xor_sync(0xffffffffu, mx0, 2));
        mx1 = fmaxf(mx1, __shfl_xor_sync(0xffffffffu, mx1, 1));
        mx1 = fmaxf(mx1, __shfl_xor_sync(0xffffffffu, mx1, 2));

        float p[4][4], sl0 = 0.f, sl1 = 0.f;
        #pragma unroll
        for (int j = 0; j < 4; j++) {
            p[j][0] = __expf(s[j][0] - mx0);
            p[j][1] = __expf(s[j][1] - mx0);
            p[j][2] = __expf(s[j][2] - mx1);
            p[j][3] = __expf(s[j][3] - mx1);
            sl0 += p[j][0] + p[j][1];
            sl1 += p[j][2] + p[j][3];
        }
        sl0 += __shfl_xor_sync(0xffffffffu, sl0, 1);
        sl0 += __shfl_xor_sync(0xffffffffu, sl0, 2);
        sl1 += __shfl_xor_sync(0xffffffffu, sl1, 1);
        sl1 += __shfl_xor_sync(0xffffffffu, sl1, 2);

        if (lc4 == 0) {
            ex[wdh * 128 + (wr + lr4)]          = mx0;
            ex[wdh * 128 + 64 + (wr + lr4)]     = sl0;
            ex[wdh * 128 + (wr + lr4 + 8)]      = mx1;
            ex[wdh * 128 + 64 + (wr + lr4 + 8)] = sl1;
        }
        __syncthreads();
        float mo0 = ex[(1 - wdh) * 128 + (wr + lr4)];
        float lo0 = ex[(1 - wdh) * 128 + 64 + (wr + lr4)];
        float mo1 = ex[(1 - wdh) * 128 + (wr + lr4 + 8)];
        float lo1 = ex[(1 - wdh) * 128 + 64 + (wr + lr4 + 8)];

        float mn0 = fmaxf(fmaxf(m0, mx0), mo0);
        float mn1 = fmaxf(fmaxf(m1, mx1), mo1);
        float f0 = __expf(mx0 - mn0), f1 = __expf(mx1 - mn1);
        float cr0 = __expf(m0 - mn0), cr1 = __expf(m1 - mn1);
        l0 = l0 * cr0 + sl0 * f0 + lo0 * __expf(mo0 - mn0);
        l1 = l1 * cr1 + sl1 * f1 + lo1 * __expf(mo1 - mn1);
        m0 = mn0; m1 = mn1;

        #pragma unroll
        for (int j = 0; j < 8; j++) {
            o[j][0] *= cr0; o[j][1] *= cr0;
            o[j][2] *= cr1; o[j][3] *= cr1;
        }

        // pack scaled probs into PV A-fragments: pa[ks2] covers kv chunk ks2*16
        unsigned pa[2][4];
        #pragma unroll
        for (int ks2 = 0; ks2 < 2; ks2++) {
            pa[ks2][0] = packbf(p[2*ks2][0] * f0,   p[2*ks2][1] * f0);
            pa[ks2][1] = packbf(p[2*ks2][2] * f1,   p[2*ks2][3] * f1);
            pa[ks2][2] = packbf(p[2*ks2+1][0] * f0, p[2*ks2+1][1] * f0);
            pa[ks2][3] = packbf(p[2*ks2+1][2] * f1, p[2*ks2+1][3] * f1);
        }

        // ---- O += P @ V over this warp's kv half, all 64 d
        #pragma unroll
        for (int ks2 = 0; ks2 < 2; ks2++) {
            #pragma unroll
            for (int jp = 0; jp < 4; jp++) {
                unsigned vb0, vb1, vb2, vb3;
                ldsm_x4_t(vb0, vb1, vb2, vb3,
                          sV0 + bo + (unsigned)((vrow + ks2 * 16) * LKW
                                                + vcol + jp * 8) * 4);
                mma_bf16(o[2*jp][0], o[2*jp][1], o[2*jp][2], o[2*jp][3],
                         pa[ks2][0], pa[ks2][1], pa[ks2][2], pa[ks2][3], vb0, vb1);
                mma_bf16(o[2*jp+1][0], o[2*jp+1][1], o[2*jp+1][2], o[2*jp+1][3],
                         pa[ks2][0], pa[ks2][1], pa[ks2][2], pa[ks2][3], vb2, vb3);
            }
        }
    }

    // ---- combine kv halves (pair of warps with same wr), normalize, store
    __syncthreads();
    float2* Of = (float2*)usm;   // [64 rows][32 float2] = 16KB, aliases K buffers
    if (wdh == 0) {
        #pragma unroll
        for (int j = 0; j < 8; j++) {
            Of[(wr + lr4) * 32 + j * 4 + lc4]     = make_float2(o[j][0], o[j][1]);
            Of[(wr + lr4 + 8) * 32 + j * 4 + lc4] = make_float2(o[j][2], o[j][3]);
        }
    }
    __syncthreads();
    if (wdh == 1) {
        float inv0 = 1.f / l0, inv1 = 1.f / l1;
        bf16* Ob = g_attn + ((size_t)(b * TQ + qblk * 64)) * CD + h * HD;
        #pragma unroll
        for (int j = 0; j < 8; j++) {
            float2 a0 = Of[(wr + lr4) * 32 + j * 4 + lc4];
            float2 a1 = Of[(wr + lr4 + 8) * 32 + j * 4 + lc4];
            int col = j * 8 + lc4 * 2;
            *(bf162*)(Ob + (size_t)(wr + lr4) * CD + col) =
                __floats2bfloat162_rn((o[j][0] + a0.x) * inv0, (o[j][1] + a0.y) * inv0);
            *(bf162*)(Ob + (size_t)(wr + lr4 + 8) * CD + col) =
                __floats2bfloat162_rn((o[j][2] + a1.x) * inv1, (o[j][3] + a1.y) * inv1);
        }
    }
}

// ---------------- host launch ----------------
extern "C" void kernel_launch(void* const* d_in, const int* in_sizes, int n_in,
                              void* d_out, int out_size)
{
    const float* x    = (const float*)d_in[0];
    const float* ctx  = (const float*)d_in[1];
    const float* Wq   = (const float*)d_in[2];
    const float* bq   = (const float*)d_in[3];
    const float* Wk   = (const float*)d_in[4];
    const float* bk   = (const float*)d_in[5];
    const float* Wv   = (const float*)d_in[6];
    const float* bv   = (const float*)d_in[7];
    const float* Wo   = (const float*)d_in[8];
    const float* bo   = (const float*)d_in[9];
    const float* ln_g = (const float*)d_in[10];
    const float* ln_b = (const float*)d_in[11];
    float* out = (float*)d_out;

    bf16 *p_xn, *p_ctx, *p_q, *p_k, *p_v, *p_attn;
    bf16 *p_wq, *p_wk, *p_wv, *p_wo;
    cudaGetSymbolAddress((void**)&p_xn,   g_xn);
    cudaGetSymbolAddress((void**)&p_ctx,  g_ctx);
    cudaGetSymbolAddress((void**)&p_q,    g_qm);
    cudaGetSymbolAddress((void**)&p_k,    g_km);
    cudaGetSymbolAddress((void**)&p_v,    g_vm);
    cudaGetSymbolAddress((void**)&p_attn, g_attn);
    cudaGetSymbolAddress((void**)&p_wq,   g_wq);
    cudaGetSymbolAddress((void**)&p_wk,   g_wk);
    cudaGetSymbolAddress((void**)&p_wv,   g_wv);
    cudaGetSymbolAddress((void**)&p_wo,   g_wo);

    // 1. quantization scales + ternary bf16 encode
    absmean_partial<<<dim3(256, 4), 256>>>(Wq, Wk, Wv, Wo);
    absmean_final<<<4, 256>>>();
    quantize_w<<<dim3(1024, 4), 256>>>(Wq, Wk, Wv, Wo);

    // 2. layernorm (bf16 out) + context convert
    layernorm_k<<<MQ / 8, 256>>>(x, ln_g, ln_b);
    convert_ctx<<<(MKV * CD) / 1024, 256>>>(ctx);

    // 3. projections
    gemm_bf16k<1><<<dim3(CD / 128, MQ  / 128), 256>>>(p_xn,  p_wq, bq, nullptr, p_q, 0);
    gemm_bf16k<1><<<dim3(CD / 128, MKV / 128), 256>>>(p_ctx, p_wk, bk, nullptr, p_k, 1);
    gemm_bf16k<1><<<dim3(CD / 128, MKV / 128), 256>>>(p_ctx, p_wv, bv, nullptr, p_v, 2);

    // 4. attention
    size_t att_smem = (size_t)(4 * 64 * LKW + 256) * 4;   // ~38 KB
    cudaFuncSetAttribute(attention_bf16,
                         cudaFuncAttributeMaxDynamicSharedMemorySize, (int)att_smem);
    attention_bf16<<<dim3(TQ / 64, CB * NH), 256, att_smem>>>();

    // 5. output projection + bias + residual (fp32 out)
    gemm_bf16k<0><<<dim3(CD / 128, MQ / 128), 256>>>(p_attn, p_wo, bo, x, out, 3);
}

// round 11
// speedup vs baseline: 6.6312x; 1.1255x over previous
#include <cuda_runtime.h>
#include <cuda_bf16.h>
#include <math.h>

// Problem constants
#define CB    4
#define TQ    1024
#define TCX   2048
#define CD    1024
#define NH    16
#define HD    64
#define MQ    (CB*TQ)    // 4096
#define MKV   (CB*TCX)   // 8192
#define ATT_SCALE 0.125f
#define LN_EPS 1e-5f
#define Q_EPS  1e-5f

typedef __nv_bfloat16  bf16;
typedef __nv_bfloat162 bf162;

// ---------------- device scratch ----------------
__device__ bf16  g_xn [MQ*CD];
__device__ bf16  g_ctx[MKV*CD];
__device__ bf16  g_qm [MQ*CD];
__device__ bf16  g_km [MKV*CD];
__device__ bf16  g_vm [MKV*CD];
__device__ bf16  g_attn[MQ*CD];
__device__ bf16  g_wq[CD*CD];
__device__ bf16  g_wk[CD*CD];
__device__ bf16  g_wv[CD*CD];
__device__ bf16  g_wo[CD*CD];
__device__ float g_partial[4][256];
__device__ float g_gamma[4];

// ---------------- helpers ----------------
__device__ __forceinline__ void mma_bf16(
    float& c0, float& c1, float& c2, float& c3,
    unsigned a0, unsigned a1, unsigned a2, unsigned a3,
    unsigned b0, unsigned b1)
{
    asm("mma.sync.aligned.m16n8k16.row.col.f32.bf16.bf16.f32 "
        "{%0,%1,%2,%3},{%4,%5,%6,%7},{%8,%9},{%0,%1,%2,%3};"
        : "+f"(c0), "+f"(c1), "+f"(c2), "+f"(c3)
        : "r"(a0), "r"(a1), "r"(a2), "r"(a3), "r"(b0), "r"(b1));
}

__device__ __forceinline__ void ldsm_x4(
    unsigned& r0, unsigned& r1, unsigned& r2, unsigned& r3, unsigned addr)
{
    asm volatile("ldmatrix.sync.aligned.m8n8.x4.shared.b16 {%0,%1,%2,%3}, [%4];"
        : "=r"(r0), "=r"(r1), "=r"(r2), "=r"(r3) : "r"(addr));
}

__device__ __forceinline__ void ldsm_x4_t(
    unsigned& r0, unsigned& r1, unsigned& r2, unsigned& r3, unsigned addr)
{
    asm volatile("ldmatrix.sync.aligned.m8n8.x4.trans.shared.b16 {%0,%1,%2,%3}, [%4];"
        : "=r"(r0), "=r"(r1), "=r"(r2), "=r"(r3) : "r"(addr));
}

__device__ __forceinline__ void cp16(unsigned s, const void* g) {
    asm volatile("cp.async.cg.shared.global [%0], [%1], 16;" :: "r"(s), "l"(g));
}
#define CP_COMMIT  asm volatile("cp.async.commit_group;" ::: "memory")
#define CP_WAIT(N) asm volatile("cp.async.wait_group %0;" :: "n"(N) : "memory")

__device__ __forceinline__ unsigned packbf(float a, float b) {
    bf162 t = __floats2bfloat162_rn(a, b);
    return *(unsigned*)&t;
}

// ---------------- |W| mean (deterministic two-pass) ----------------
__global__ __launch_bounds__(256) void absmean_partial(
    const float* __restrict__ W0, const float* __restrict__ W1,
    const float* __restrict__ W2, const float* __restrict__ W3)
{
    const float* W = (blockIdx.y == 0) ? W0 : (blockIdx.y == 1) ? W1
                   : (blockIdx.y == 2) ? W2 : W3;
    __shared__ float sh[256];
    int base = blockIdx.x * 4096;
    float acc = 0.f;
    for (int i = threadIdx.x; i < 4096; i += 256)
        acc += fabsf(W[base + i]);
    sh[threadIdx.x] = acc;
    __syncthreads();
    for (int o = 128; o > 0; o >>= 1) {
        if (threadIdx.x < o) sh[threadIdx.x] += sh[threadIdx.x + o];
        __syncthreads();
    }
    if (threadIdx.x == 0) g_partial[blockIdx.y][blockIdx.x] = sh[0];
}

__global__ __launch_bounds__(256) void absmean_final()
{
    __shared__ float sh[256];
    sh[threadIdx.x] = g_partial[blockIdx.x][threadIdx.x];
    __syncthreads();
    for (int o = 128; o > 0; o >>= 1) {
        if (threadIdx.x < o) sh[threadIdx.x] += sh[threadIdx.x + o];
        __syncthreads();
    }
    if (threadIdx.x == 0)
        g_gamma[blockIdx.x] = sh[0] / (float)(CD * CD);
}

// ---------------- ternary quantization (ternary EXACT in bf16) ----------------
__global__ __launch_bounds__(256) void quantize_w(
    const float* __restrict__ W0, const float* __restrict__ W1,
    const float* __restrict__ W2, const float* __restrict__ W3)
{
    int w = blockIdx.y;
    const float* W = (w == 0) ? W0 : (w == 1) ? W1 : (w == 2) ? W2 : W3;
    bf16* Wd = (w == 0) ? g_wq : (w == 1) ? g_wk : (w == 2) ? g_wv : g_wo;
    float g  = g_gamma[w];
    float gd = g + Q_EPS;
    int idx0 = blockIdx.x * 256 + threadIdx.x;
    #pragma unroll
    for (int r = 0; r < 4; r++) {
        int i = idx0 + r * 262144;
        float t = rintf(W[i] / gd);
        t = fminf(fmaxf(t, -1.f), 1.f);
        Wd[i] = __float2bfloat16(t);
    }
}

// ---------------- layernorm: warp per row ----------------
__global__ __launch_bounds__(256) void layernorm_k(
    const float* __restrict__ x, const float* __restrict__ gamma,
    const float* __restrict__ beta)
{
    int row = blockIdx.x * 8 + (threadIdx.x >> 5);
    int lane = threadIdx.x & 31;
    const float4* xr = (const float4*)(x + (size_t)row * CD);
    float4 v[8];
    float a = 0.f, b2 = 0.f;
    #pragma unroll
    for (int i = 0; i < 8; i++) {
        v[i] = xr[lane + i * 32];
        a  += v[i].x + v[i].y + v[i].z + v[i].w;
        b2 += v[i].x * v[i].x + v[i].y * v[i].y + v[i].z * v[i].z + v[i].w * v[i].w;
    }
    #pragma unroll
    for (int o = 16; o > 0; o >>= 1) {
        a  += __shfl_xor_sync(0xffffffffu, a, o);
        b2 += __shfl_xor_sync(0xffffffffu, b2, o);
    }
    float mu = a / (float)CD;
    float var = b2 / (float)CD - mu * mu;
    float rstd = rsqrtf(var + LN_EPS);
    uint2* orow = (uint2*)(g_xn + (size_t)row * CD);
    const float4* gm = (const float4*)gamma;
    const float4* bt = (const float4*)beta;
    #pragma unroll
    for (int i = 0; i < 8; i++) {
        float4 g4 = gm[lane + i * 32];
        float4 b4 = bt[lane + i * 32];
        float y0 = (v[i].x - mu) * rstd * g4.x + b4.x;
        float y1 = (v[i].y - mu) * rstd * g4.y + b4.y;
        float y2 = (v[i].z - mu) * rstd * g4.z + b4.z;
        float y3 = (v[i].w - mu) * rstd * g4.w + b4.w;
        uint2 w;
        w.x = packbf(y0, y1);
        w.y = packbf(y2, y3);
        orow[lane + i * 32] = w;
    }
}

// ---------------- context fp32 -> bf16 ----------------
__global__ __launch_bounds__(256) void convert_ctx(const float* __restrict__ c)
{
    size_t i = (size_t)(blockIdx.x * 256 + threadIdx.x) * 4;
    float4 v = *(const float4*)&c[i];
    bf162* o = (bf162*)&g_ctx[i];
    o[0] = __floats2bfloat162_rn(v.x, v.y);
    o[1] = __floats2bfloat162_rn(v.z, v.w);
}

// ---------------- bf16 tensor-core NT GEMM ----------------
// BM=BN=128, BK=32, 4 warps (2x2), warp tile 64x64, 3-stage cp.async,
// one __syncthreads per BK tile.
#define GLDW 20
#define NSTG 3
#define STGW (128 * GLDW)     // words per matrix per stage

template<int BF16OUT>
__global__ __launch_bounds__(128) void gemm_bf16k(
    const bf16* __restrict__ A, const bf16* __restrict__ W,
    const float* __restrict__ bias, const float* __restrict__ resid,
    void* __restrict__ outp, int gidx)
{
    extern __shared__ unsigned sm[];
    const int tid = threadIdx.x, lane = tid & 31, wid = tid >> 5;
    const int bm = blockIdx.y * 128, bn = blockIdx.x * 128;
    const int wm = (wid >> 1) * 64, wn = (wid & 1) * 64;
    const int lr4 = lane >> 2, lc4 = lane & 3;
    const int g8 = lane >> 3, r8 = lane & 7;

    const unsigned sA = (unsigned)__cvta_generic_to_shared(sm);
    const unsigned sW = sA + NSTG * STGW * 4;

    // load mapping: 512 16B chunks per matrix per stage, 4 per thread
    const int lrow0 = tid >> 2;        // 0..31 (+u*32)
    const int lch   = tid & 3;         // 16B chunk in row
    const unsigned lso = (unsigned)(lrow0 * GLDW + lch * 4) * 4;

    // ldmatrix lane offsets
    const int arow = ((g8 & 1) ? 8 : 0) + r8;
    const int acol = (g8 >= 2) ? 4 : 0;
    const int brow = ((g8 >= 2) ? 8 : 0) + r8;
    const int bcol = (g8 & 1) ? 4 : 0;

    float c[4][8][4];
    #pragma unroll
    for (int i = 0; i < 4; i++)
        #pragma unroll
        for (int j = 0; j < 8; j++)
            #pragma unroll
            for (int r = 0; r < 4; r++) c[i][j][r] = 0.f;

    const int NT = CD / 32;

    // prologue: stages 0,1
    #pragma unroll
    for (int s = 0; s < 2; s++) {
        const unsigned bofs = (unsigned)(s * STGW * 4);
        #pragma unroll
        for (int u = 0; u < 4; u++) {
            int row = lrow0 + u * 32;
            unsigned so = bofs + lso + (unsigned)(u * 32 * GLDW * 4);
            cp16(sA + so, A + (size_t)(bm + row) * CD + s * 32 + lch * 8);
            cp16(sW + so, W + (size_t)(bn + row) * CD + s * 32 + lch * 8);
        }
        CP_COMMIT;
    }

    for (int kt = 0; kt < NT; kt++) {
        CP_WAIT(1);
        __syncthreads();
        // prefetch stage kt+2 (buffer was consumed in iter kt-1)
        if (kt + 2 < NT) {
            int sb = (kt + 2) % NSTG;
            const unsigned bofs = (unsigned)(sb * STGW * 4);
            const int k0 = (kt + 2) * 32;
            #pragma unroll
            for (int u = 0; u < 4; u++) {
                int row = lrow0 + u * 32;
                unsigned so = bofs + lso + (unsigned)(u * 32 * GLDW * 4);
                cp16(sA + so, A + (size_t)(bm + row) * CD + k0 + lch * 8);
                cp16(sW + so, W + (size_t)(bn + row) * CD + k0 + lch * 8);
            }
        }
        CP_COMMIT;   // always commit (empty at tail) to keep group numbering

        const unsigned bufo = (unsigned)((kt % NSTG) * STGW * 4);
        #pragma unroll
        for (int ks = 0; ks < 2; ks++) {
            unsigned a[4][4], b[4][4];
            #pragma unroll
            for (int i = 0; i < 4; i++)
                ldsm_x4(a[i][0], a[i][1], a[i][2], a[i][3],
                        sA + bufo + (unsigned)((wm + i * 16 + arow) * GLDW
                                               + acol + ks * 8) * 4);
            #pragma unroll
            for (int jp = 0; jp < 4; jp++)
                ldsm_x4(b[jp][0], b[jp][1], b[jp][2], b[jp][3],
                        sW + bufo + (unsigned)((wn + jp * 16 + brow) * GLDW
                                               + bcol + ks * 8) * 4);
            #pragma unroll
            for (int i = 0; i < 4; i++)
                #pragma unroll
                for (int jp = 0; jp < 4; jp++) {
                    mma_bf16(c[i][2*jp][0], c[i][2*jp][1], c[i][2*jp][2], c[i][2*jp][3],
                             a[i][0], a[i][1], a[i][2], a[i][3], b[jp][0], b[jp][1]);
                    mma_bf16(c[i][2*jp+1][0], c[i][2*jp+1][1], c[i][2*jp+1][2], c[i][2*jp+1][3],
                             a[i][0], a[i][1], a[i][2], a[i][3], b[jp][2], b[jp][3]);
                }
        }
    }

    const float g = g_gamma[gidx];
    #pragma unroll
    for (int i = 0; i < 4; i++) {
        int r0 = bm + wm + i * 16 + lr4;
        #pragma unroll
        for (int j = 0; j < 8; j++) {
            int col = bn + wn + j * 8 + lc4 * 2;
            float b0v = bias[col], b1v = bias[col + 1];
            size_t i00 = (size_t)r0 * CD + col;
            size_t i10 = (size_t)(r0 + 8) * CD + col;
            float v00 = c[i][j][0] * g + b0v;
            float v01 = c[i][j][1] * g + b1v;
            float v10 = c[i][j][2] * g + b0v;
            float v11 = c[i][j][3] * g + b1v;
            if (BF16OUT) {
                bf162* ob = (bf162*)outp;
                ob[i00 >> 1] = __floats2bfloat162_rn(v00, v01);
                ob[i10 >> 1] = __floats2bfloat162_rn(v10, v11);
            } else {
                float* of = (float*)outp;
                of[i00]     = v00 + resid[i00];
                of[i00 + 1] = v01 + resid[i00 + 1];
                of[i10]     = v10 + resid[i10];
                of[i10 + 1] = v11 + resid[i10 + 1];
            }
        }
    }
}

// ---------------- flash attention: register softmax, 3-stage cp.async ----------------
// 64 q-rows/block, kv tiles of 64. 8 warps: 4 row groups x 2 kv-halves.
#define LKW 36
#define KVSTG (64 * LKW)    // words per matrix per stage

__global__ __launch_bounds__(256) void attention_bf16()
{
    extern __shared__ unsigned usm[];
    // K: 3 stages | V: 3 stages | ex stats (256 floats)
    float* ex = (float*)(usm + 6 * KVSTG);

    const int tid = threadIdx.x, lane = tid & 31, wid = tid >> 5;
    const int qblk = blockIdx.x, bh = blockIdx.y;
    const int b = bh >> 4, h = bh & 15;
    const int lr4 = lane >> 2, lc4 = lane & 3;
    const int g8 = lane >> 3, r8 = lane & 7;
    const int wr = (wid >> 1) * 16;
    const int wdh = wid & 1;
    const int wd = wdh * 32;

    const bf16* Qb = g_qm + ((size_t)(b * TQ + qblk * 64)) * CD + h * HD;
    const bf16* Kb = g_km + ((size_t)(b * TCX)) * CD + h * HD;
    const bf16* Vb = g_vm + ((size_t)(b * TCX)) * CD + h * HD;

    const unsigned sbase = (unsigned)__cvta_generic_to_shared(usm);
    const unsigned sK0 = sbase;
    const unsigned sV0 = sbase + 3u * KVSTG * 4;

    // ---- stage Q (scaled) into K buffer 0, extract A-fragments, then free it
    const bf162 sc2 = __floats2bfloat162_rn(ATT_SCALE, ATT_SCALE);
    #pragma unroll
    for (int it = 0; it < 2; it++) {
        int i = tid + it * 256;
        int row = i >> 3, d0 = (i & 7) * 8;
        uint4 v = *(const uint4*)(Qb + (size_t)row * CD + d0);
        bf162* pv = (bf162*)&v;
        #pragma unroll
        for (int m = 0; m < 4; m++) pv[m] = __hmul2(pv[m], sc2);
        *(uint4*)&usm[row * LKW + (i & 7) * 4] = v;
    }
    __syncthreads();
    unsigned q[4][4];
    {
        int qrow = wr + ((g8 & 1) ? 8 : 0) + r8;
        int qcol = (g8 >= 2) ? 4 : 0;
        #pragma unroll
        for (int ks = 0; ks < 4; ks++)
            ldsm_x4(q[ks][0], q[ks][1], q[ks][2], q[ks][3],
                    sK0 + (unsigned)(qrow * LKW + qcol + ks * 8) * 4);
    }
    __syncthreads();

    // ---- prologue: tiles 0,1 -> buffers 0,1
    #pragma unroll
    for (int s = 0; s < 2; s++) {
        const unsigned bofs = (unsigned)(s * KVSTG * 4);
        #pragma unroll
        for (int u = 0; u < 2; u++) {
            int cc = tid + u * 256;
            int row = cc >> 3, qc = cc & 7;
            unsigned so = bofs + (unsigned)(row * LKW + qc * 4) * 4;
            cp16(sK0 + so, Kb + (size_t)(s * 64 + row) * CD + qc * 8);
            cp16(sV0 + so, Vb + (size_t)(s * 64 + row) * CD + qc * 8);
        }
        CP_COMMIT;
    }

    float m0 = -1e30f, m1 = -1e30f, l0 = 0.f, l1 = 0.f;
    float o[8][4];
    #pragma unroll
    for (int j = 0; j < 8; j++)
        #pragma unroll
        for (int r = 0; r < 4; r++) o[j][r] = 0.f;

    const int krow = wd + ((g8 >= 2) ? 8 : 0) + r8;
    const int kcol = (g8 & 1) ? 4 : 0;
    const int vrow = wd + ((g8 & 1) ? 8 : 0) + r8;
    const int vcol = (g8 >= 2) ? 4 : 0;

    const int NT = TCX / 64;
    for (int t = 0; t < NT; t++) {
        CP_WAIT(1);
        __syncthreads();     // tile t visible; buffer (t+2)%3 free (read in t-1)
        if (t + 2 < NT) {
            const unsigned bofs = (unsigned)(((t + 2) % 3) * KVSTG * 4);
            #pragma unroll
            for (int u = 0; u < 2; u++) {
                int cc = tid + u * 256;
                int row = cc >> 3, qc = cc & 7;
                unsigned so = bofs + (unsigned)(row * LKW + qc * 4) * 4;
                cp16(sK0 + so, Kb + (size_t)((t + 2) * 64 + row) * CD + qc * 8);
                cp16(sV0 + so, Vb + (size_t)((t + 2) * 64 + row) * CD + qc * 8);
            }
        }
        CP_COMMIT;

        const unsigned bo = (unsigned)((t % 3) * KVSTG * 4);

        // ---- S = Q K^T (regs)
        float s[4][4];
        #pragma unroll
        for (int j = 0; j < 4; j++)
            #pragma unroll
            for (int r = 0; r < 4; r++) s[j][r] = 0.f;
        #pragma unroll
        for (int ks = 0; ks < 4; ks++) {
            #pragma unroll
            for (int jp = 0; jp < 2; jp++) {
                unsigned kb0, kb1, kb2, kb3;
                ldsm_x4(kb0, kb1, kb2, kb3,
                        sK0 + bo + (unsigned)((krow + jp * 16) * LKW + kcol + ks * 8) * 4);
                mma_bf16(s[2*jp][0], s[2*jp][1], s[2*jp][2], s[2*jp][3],
                         q[ks][0], q[ks][1], q[ks][2], q[ks][3], kb0, kb1);
                mma_bf16(s[2*jp+1][0], s[2*jp+1][1], s[2*jp+1][2], s[2*jp+1][3],
                         q[ks][0], q[ks][1], q[ks][2], q[ks][3], kb2, kb3);
            }
        }

        // ---- softmax partials (this warp's 32 kv cols)
        float mx0 = -1e30f, mx1 = -1e30f;
        #pragma unroll
        for (int j = 0; j < 4; j++) {
            mx0 = fmaxf(mx0, fmaxf(s[j][0], s[j][1]));
            mx1 = fmaxf(mx1, fmaxf(s[j][2], s[j][3]));
        }
        mx0 = fmaxf(mx0, __shfl_xor_sync(0xffffffffu, mx0, 1));
        mx0 = fmaxf(mx0, __shfl_xor_sync(0xffffffffu, mx0, 2));
        mx1 = fmaxf(mx1, __shfl_xor_sync(0xffffffffu, mx1, 1));
        mx1 = fmaxf(mx1, __shfl_xor_sync(0xffffffffu, mx1, 2));

        float p[4][4], sl0 = 0.f, sl1 = 0.f;
        #pragma unroll
        for (int j = 0; j < 4; j++) {
            p[j][0] = __expf(s[j][0] - mx0);
            p[j][1] = __expf(s[j][1] - mx0);
            p[j][2] = __expf(s[j][2] - mx1);
            p[j][3] = __expf(s[j][3] - mx1);
            sl0 += p[j][0] + p[j][1];
            sl1 += p[j][2] + p[j][3];
        }
        sl0 += __shfl_xor_sync(0xffffffffu, sl0, 1);
        sl0 += __shfl_xor_sync(0xffffffffu, sl0, 2);
        sl1 += __shfl_xor_sync(0xffffffffu, sl1, 1);
        sl1 += __shfl_xor_sync(0xffffffffu, sl1, 2);

        if (lc4 == 0) {
            ex[wdh * 128 + (wr + lr4)]          = mx0;
            ex[wdh * 128 + 64 + (wr + lr4)]     = sl0;
            ex[wdh * 128 + (wr + lr4 + 8)]      = mx1;
            ex[wdh * 128 + 64 + (wr + lr4 + 8)] = sl1;
        }
        __syncthreads();
        float mo0 = ex[(1 - wdh) * 128 + (wr + lr4)];
        float lo0 = ex[(1 - wdh) * 128 + 64 + (wr + lr4)];
        float mo1 = ex[(1 - wdh) * 128 + (wr + lr4 + 8)];
        float lo1 = ex[(1 - wdh) * 128 + 64 + (wr + lr4 + 8)];

        float mn0 = fmaxf(fmaxf(m0, mx0), mo0);
        float mn1 = fmaxf(fmaxf(m1, mx1), mo1);
        float f0 = __expf(mx0 - mn0), f1 = __expf(mx1 - mn1);
        float cr0 = __expf(m0 - mn0), cr1 = __expf(m1 - mn1);
        l0 = l0 * cr0 + sl0 * f0 + lo0 * __expf(mo0 - mn0);
        l1 = l1 * cr1 + sl1 * f1 + lo1 * __expf(mo1 - mn1);
        m0 = mn0; m1 = mn1;

        #pragma unroll
        for (int j = 0; j < 8; j++) {
            o[j][0] *= cr0; o[j][1] *= cr0;
            o[j][2] *= cr1; o[j][3] *= cr1;
        }

        unsigned pa[2][4];
        #pragma unroll
        for (int ks2 = 0; ks2 < 2; ks2++) {
            pa[ks2][0] = packbf(p[2*ks2][0] * f0,   p[2*ks2][1] * f0);
            pa[ks2][1] = packbf(p[2*ks2][2] * f1,   p[2*ks2][3] * f1);
            pa[ks2][2] = packbf(p[2*ks2+1][0] * f0, p[2*ks2+1][1] * f0);
            pa[ks2][3] = packbf(p[2*ks2+1][2] * f1, p[2*ks2+1][3] * f1);
        }

        // ---- O += P @ V over this warp's kv half, all 64 d
        #pragma unroll
        for (int ks2 = 0; ks2 < 2; ks2++) {
            #pragma unroll
            for (int jp = 0; jp < 4; jp++) {
                unsigned vb0, vb1, vb2, vb3;
                ldsm_x4_t(vb0, vb1, vb2, vb3,
                          sV0 + bo + (unsigned)((vrow + ks2 * 16) * LKW
                                                + vcol + jp * 8) * 4);
                mma_bf16(o[2*jp][0], o[2*jp][1], o[2*jp][2], o[2*jp][3],
                         pa[ks2][0], pa[ks2][1], pa[ks2][2], pa[ks2][3], vb0, vb1);
                mma_bf16(o[2*jp+1][0], o[2*jp+1][1], o[2*jp+1][2], o[2*jp+1][3],
                         pa[ks2][0], pa[ks2][1], pa[ks2][2], pa[ks2][3], vb2, vb3);
            }
        }
    }

    // ---- combine kv halves, normalize, store
    __syncthreads();
    float2* Of = (float2*)usm;   // 16 KB, aliases K buffers
    if (wdh == 0) {
        #pragma unroll
        for (int j = 0; j < 8; j++) {
            Of[(wr + lr4) * 32 + j * 4 + lc4]     = make_float2(o[j][0], o[j][1]);
            Of[(wr + lr4 + 8) * 32 + j * 4 + lc4] = make_float2(o[j][2], o[j][3]);
        }
    }
    __syncthreads();
    if (wdh == 1) {
        float inv0 = 1.f / l0, inv1 = 1.f / l1;
        bf16* Ob = g_attn + ((size_t)(b * TQ + qblk * 64)) * CD + h * HD;
        #pragma unroll
        for (int j = 0; j < 8; j++) {
            float2 a0 = Of[(wr + lr4) * 32 + j * 4 + lc4];
            float2 a1 = Of[(wr + lr4 + 8) * 32 + j * 4 + lc4];
            int col = j * 8 + lc4 * 2;
            *(bf162*)(Ob + (size_t)(wr + lr4) * CD + col) =
                __floats2bfloat162_rn((o[j][0] + a0.x) * inv0, (o[j][1] + a0.y) * inv0);
            *(bf162*)(Ob + (size_t)(wr + lr4 + 8) * CD + col) =
                __floats2bfloat162_rn((o[j][2] + a1.x) * inv1, (o[j][3] + a1.y) * inv1);
        }
    }
}

// ---------------- host launch ----------------
extern "C" void kernel_launch(void* const* d_in, const int* in_sizes, int n_in,
                              void* d_out, int out_size)
{
    const float* x    = (const float*)d_in[0];
    const float* ctx  = (const float*)d_in[1];
    const float* Wq   = (const float*)d_in[2];
    const float* bq   = (const float*)d_in[3];
    const float* Wk   = (const float*)d_in[4];
    const float* bk   = (const float*)d_in[5];
    const float* Wv   = (const float*)d_in[6];
    const float* bv   = (const float*)d_in[7];
    const float* Wo   = (const float*)d_in[8];
    const float* bo   = (const float*)d_in[9];
    const float* ln_g = (const float*)d_in[10];
    const float* ln_b = (const float*)d_in[11];
    float* out = (float*)d_out;

    bf16 *p_xn, *p_ctx, *p_q, *p_k, *p_v, *p_attn;
    bf16 *p_wq, *p_wk, *p_wv, *p_wo;
    cudaGetSymbolAddress((void**)&p_xn,   g_xn);
    cudaGetSymbolAddress((void**)&p_ctx,  g_ctx);
    cudaGetSymbolAddress((void**)&p_q,    g_qm);
    cudaGetSymbolAddress((void**)&p_k,    g_km);
    cudaGetSymbolAddress((void**)&p_v,    g_vm);
    cudaGetSymbolAddress((void**)&p_attn, g_attn);
    cudaGetSymbolAddress((void**)&p_wq,   g_wq);
    cudaGetSymbolAddress((void**)&p_wk,   g_wk);
    cudaGetSymbolAddress((void**)&p_wv,   g_wv);
    cudaGetSymbolAddress((void**)&p_wo,   g_wo);

    // 1. quantization scales + ternary bf16 encode
    absmean_partial<<<dim3(256, 4), 256>>>(Wq, Wk, Wv, Wo);
    absmean_final<<<4, 256>>>();
    quantize_w<<<dim3(1024, 4), 256>>>(Wq, Wk, Wv, Wo);

    // 2. layernorm (bf16 out) + context convert
    layernorm_k<<<MQ / 8, 256>>>(x, ln_g, ln_b);
    convert_ctx<<<(MKV * CD) / 1024, 256>>>(ctx);

    // 3. projections
    const int gemm_smem = NSTG * STGW * 2 * 4;   // 61440 B
    cudaFuncSetAttribute(gemm_bf16k<1>,
                         cudaFuncAttributeMaxDynamicSharedMemorySize, gemm_smem);
    cudaFuncSetAttribute(gemm_bf16k<0>,
                         cudaFuncAttributeMaxDynamicSharedMemorySize, gemm_smem);
    gemm_bf16k<1><<<dim3(CD / 128, MQ  / 128), 128, gemm_smem>>>(p_xn,  p_wq, bq, nullptr, p_q, 0);
    gemm_bf16k<1><<<dim3(CD / 128, MKV / 128), 128, gemm_smem>>>(p_ctx, p_wk, bk, nullptr, p_k, 1);
    gemm_bf16k<1><<<dim3(CD / 128, MKV / 128), 128, gemm_smem>>>(p_ctx, p_wv, bv, nullptr, p_v, 2);

    // 4. attention
    const int att_smem = (6 * KVSTG + 256) * 4;  // ~56 KB
    cudaFuncSetAttribute(attention_bf16,
                         cudaFuncAttributeMaxDynamicSharedMemorySize, att_smem);
    attention_bf16<<<dim3(TQ / 64, CB * NH), 256, att_smem>>>();

    // 5. output projection + bias + residual (fp32 out)
    gemm_bf16k<0><<<dim3(CD / 128, MQ / 128), 128, gemm_smem>>>(p_attn, p_wo, bo, x, out, 3);
}